// round 9
// baseline (speedup 1.0000x reference)
#include <cuda_runtime.h>

typedef unsigned long long u64;
typedef unsigned int u32;

__device__ __forceinline__ u64 bc2(float v){ u64 r; asm("mov.b64 %0, {%1,%1};":"=l"(r):"f"(v)); return r; }
__device__ __forceinline__ void fma2(u64& c, u64 a, u64 b){ asm("fma.rn.f32x2 %0, %1, %2, %0;":"+l"(c):"l"(a),"l"(b)); }
__device__ __forceinline__ float2 up2(u64 v){ float lo,hi; asm("mov.b64 {%0,%1}, %2;":"=f"(lo),"=f"(hi):"l"(v)); return make_float2(lo,hi); }
__device__ __forceinline__ u32 sptr(const void* p){ return (u32)__cvta_generic_to_shared(p); }
__device__ __forceinline__ void cp16z(u32 dst, const float* src, bool ok){
    int sz = ok ? 16 : 0;
    asm volatile("cp.async.cg.shared.global [%0], [%1], 16, %2;"::"r"(dst),"l"(src),"r"(sz));
}
__device__ __forceinline__ void cpcommit(){ asm volatile("cp.async.commit_group;"); }
__device__ __forceinline__ void cpwait1(){ asm volatile("cp.async.wait_group 1;"); }

// -------- scratch --------
__device__ float g_xt[64*256*512];
__device__ float g_h1[64*256*512];
__device__ float g_h2[64*256*256];
__device__ float g_h3[64*512*256];
__device__ float g_h4[64*512*128];
__device__ float g_z [64*512*128];
__device__ float g_zq[64*512*128];
__device__ float g_zqr[64*512*128];
__device__ float g_g1[64*512*128];
__device__ float g_g2[64*512*256];
__device__ float g_g3[64*256*256];
__device__ float g_g4[64*256*512];
__device__ float g_wt[5373952];
__device__ float g_cbn[512];
__device__ float g_zn[64*128];
__device__ float g_bs[64*4*128];
__device__ int   g_bi[64*4*128];
__device__ int   g_idx[64*128];
__device__ double g_part[256];

// -------- fused weight re-layout for all 10 layers --------
struct W10 { const float* p[10]; };

__global__ void wtr_all_k(W10 a, float* __restrict__ wt)
{
    const int CINL[10]  = {256,256,256,512,512,512,512,512,256,256};
    const int COUTL[10] = {256,256,512,512,512,512,512,256,256,256};
    const int KL[10]    = {3,4,3,4,3,3,4,3,4,3};
    const int TL[10]    = {0,0,0,0,0,0,1,0,1,0};
    const int OFF[11]   = {0,196608,458752,851968,1900544,2686976,
                           3473408,4521984,4915200,5177344,5373952};
    int gi = blockIdx.x*256 + threadIdx.x;
    if (gi >= 5373952) return;
    int l = 0;
#pragma unroll
    for (int q = 1; q < 10; q++) if (gi >= OFF[q]) l = q;
    int i = gi - OFF[l];
    int COUT = COUTL[l], CIN = CINL[l], K = KL[l];
    int co = i % COUT, r = i / COUT, ci = r % CIN, k = r / CIN;
    wt[gi] = TL[l] ? a.p[l][((size_t)ci*COUT + co)*K + k]
                   : a.p[l][((size_t)co*CIN + ci)*K + k];
}

// -------- [B,T,F] -> [B,F,T] --------
__global__ void transpose_in_k(const float* __restrict__ x, float* __restrict__ xt)
{
    __shared__ float tile[32][33];
    int b = blockIdx.z, t0 = blockIdx.x*32, f0 = blockIdx.y*32;
    int tx = threadIdx.x, ty = threadIdx.y;
#pragma unroll
    for (int r = 0; r < 32; r += 8)
        tile[ty+r][tx] = x[((size_t)b*512 + (t0+ty+r))*256 + f0+tx];
    __syncthreads();
#pragma unroll
    for (int r = 0; r < 32; r += 8)
        xt[((size_t)b*256 + (f0+ty+r))*512 + t0+tx] = tile[tx][ty+r];
}

// -------- conv1d, 256 thr, 128co x 128t tile, CI_TILE=8, double-buffered --------
template <int CIN, int COUT, int K, int STRIDE, bool RELU, bool TROUT>
__global__ __launch_bounds__(256, 2)
void conv1d_k(const float* __restrict__ x, const float* __restrict__ wt,
              const float* __restrict__ bias, float* __restrict__ y,
              int Tin, int Tout)
{
    constexpr int XPAD = (STRIDE==1) ? 136 : 264;
    constexpr int NIT  = CIN/8;
    constexpr int WST  = K*8*128;
    constexpr int XST  = 8*XPAD;
    extern __shared__ float sm[];
    float* Wb = sm;
    float* Xb = sm + 2*WST;

    int b = blockIdx.z, co0 = blockIdx.y*128, t0 = blockIdx.x*128;
    int tid = threadIdx.x, t_th = tid & 15, co_th = tid >> 4;
    int gbase = t0*STRIDE - 4;

    u64 acc[4][8];
#pragma unroll
    for (int u = 0; u < 4; u++)
#pragma unroll
        for (int j = 0; j < 8; j++) acc[u][j] = 0ULL;

    auto fill = [&](int s, int ci0){
        float* W = Wb + s*WST;
#pragma unroll
        for (int i = tid; i < K*8*32; i += 256) {
            int q = i & 31, r = i >> 5;        // r = k*8+ci
            int ci = r & 7, k = r >> 3;
            cp16z(sptr(W + r*128 + q*4),
                  wt + ((size_t)(k*CIN + ci0+ci))*COUT + co0 + q*4, true);
        }
        float* X = Xb + s*XST;
        for (int i = tid; i < 8*(XPAD/4); i += 256) {
            int ci = i / (XPAD/4), c = i % (XPAD/4);
            int gt = gbase + 4*c;
            bool ok = (gt >= 0) && (gt < Tin);
            const float* src = x + ((size_t)b*CIN + ci0+ci)*Tin + (ok ? gt : 0);
            cp16z(sptr(X + ci*XPAD + 4*c), src, ok);
        }
    };

    fill(0, 0); cpcommit();
#pragma unroll 1
    for (int it = 0; it < NIT; it++) {
        int cur = it & 1;
        if (it+1 < NIT) fill(cur^1, (it+1)*8);
        cpcommit();
        cpwait1();
        __syncthreads();
        const float* W = Wb + cur*WST;
        const float* X = Xb + cur*XST;
#pragma unroll
        for (int ci = 0; ci < 8; ci++) {
            constexpr int NXL = (STRIDE==1) ? 4 : 6;
            float xr[NXL*4];
            const float* xp = X + ci*XPAD + t_th*8*STRIDE;
#pragma unroll
            for (int q = 0; q < NXL; q++) {
                float4 v = *reinterpret_cast<const float4*>(xp + 4*q);
                xr[4*q]=v.x; xr[4*q+1]=v.y; xr[4*q+2]=v.z; xr[4*q+3]=v.w;
            }
            u64 wp[K][4];
#pragma unroll
            for (int k = 0; k < K; k++) {
                const ulonglong2* wq = reinterpret_cast<const ulonglong2*>(W + (k*8+ci)*128 + co_th*8);
                ulonglong2 a = wq[0], bq = wq[1];
                wp[k][0]=a.x; wp[k][1]=a.y; wp[k][2]=bq.x; wp[k][3]=bq.y;
            }
            if constexpr (STRIDE==1) {
                u64 x0 = bc2(xr[3]), x1 = bc2(xr[4]);
#pragma unroll
                for (int j = 0; j < 8; j++) {
                    u64 x2 = bc2(xr[j+5]);
#pragma unroll
                    for (int u = 0; u < 4; u++) fma2(acc[u][j], wp[0][u], x0);
#pragma unroll
                    for (int u = 0; u < 4; u++) fma2(acc[u][j], wp[1][u], x1);
#pragma unroll
                    for (int u = 0; u < 4; u++) fma2(acc[u][j], wp[2][u], x2);
                    x0 = x1; x1 = x2;
                }
            } else {
                u64 x0 = bc2(xr[3]), x1 = bc2(xr[4]);
#pragma unroll
                for (int j = 0; j < 8; j++) {
                    u64 x2 = bc2(xr[2*j+5]), x3 = bc2(xr[2*j+6]);
#pragma unroll
                    for (int u = 0; u < 4; u++) fma2(acc[u][j], wp[0][u], x0);
#pragma unroll
                    for (int u = 0; u < 4; u++) fma2(acc[u][j], wp[1][u], x1);
#pragma unroll
                    for (int u = 0; u < 4; u++) fma2(acc[u][j], wp[2][u], x2);
#pragma unroll
                    for (int u = 0; u < 4; u++) fma2(acc[u][j], wp[3][u], x3);
                    x0 = x2; x1 = x3;
                }
            }
        }
        __syncthreads();
    }

    float bb[8];
    {
        float4 b0 = *reinterpret_cast<const float4*>(&bias[co0+co_th*8]);
        float4 b1 = *reinterpret_cast<const float4*>(&bias[co0+co_th*8+4]);
        bb[0]=b0.x; bb[1]=b0.y; bb[2]=b0.z; bb[3]=b0.w;
        bb[4]=b1.x; bb[5]=b1.y; bb[6]=b1.z; bb[7]=b1.w;
    }
    int tout0 = t0 + t_th*8;
    if (!TROUT) {
#pragma unroll
        for (int u = 0; u < 4; u++) {
            float ra[8], rb[8];
#pragma unroll
            for (int j = 0; j < 8; j++) {
                float2 f = up2(acc[u][j]);
                float va = f.x + bb[2*u], vb = f.y + bb[2*u+1];
                ra[j] = RELU ? fmaxf(va, 0.f) : va;
                rb[j] = RELU ? fmaxf(vb, 0.f) : vb;
            }
            float* ya = &y[((size_t)b*COUT + co0+co_th*8+2*u)*Tout + tout0];
            float* yb = &y[((size_t)b*COUT + co0+co_th*8+2*u+1)*Tout + tout0];
            *reinterpret_cast<float4*>(ya)   = make_float4(ra[0],ra[1],ra[2],ra[3]);
            *reinterpret_cast<float4*>(ya+4) = make_float4(ra[4],ra[5],ra[6],ra[7]);
            *reinterpret_cast<float4*>(yb)   = make_float4(rb[0],rb[1],rb[2],rb[3]);
            *reinterpret_cast<float4*>(yb+4) = make_float4(rb[4],rb[5],rb[6],rb[7]);
        }
    } else {
#pragma unroll
        for (int j = 0; j < 8; j++) {
            float r[8];
#pragma unroll
            for (int u = 0; u < 4; u++) {
                float2 f = up2(acc[u][j]);
                float va = f.x + bb[2*u], vb = f.y + bb[2*u+1];
                r[2*u]   = RELU ? fmaxf(va, 0.f) : va;
                r[2*u+1] = RELU ? fmaxf(vb, 0.f) : vb;
            }
            float* yp = &y[((size_t)b*Tout + tout0+j)*COUT + co0+co_th*8];
            *reinterpret_cast<float4*>(yp)   = make_float4(r[0],r[1],r[2],r[3]);
            *reinterpret_cast<float4*>(yp+4) = make_float4(r[4],r[5],r[6],r[7]);
        }
    }
}

// -------- convT1d s2 p1 K4, CI_TILE=8, double-buffered --------
template <int CIN, int COUT>
__global__ __launch_bounds__(256, 2)
void convT1d_k(const float* __restrict__ x, const float* __restrict__ wt,
               const float* __restrict__ bias, float* __restrict__ y,
               int Tin, int Tout)
{
    constexpr int XPAD = 72;
    constexpr int NIT  = CIN/8;
    constexpr int WST  = 4*8*128;
    constexpr int XST  = 8*XPAD;
    extern __shared__ float sm[];
    float* Wb = sm;
    float* Xb = sm + 2*WST;

    int b = blockIdx.z, co0 = blockIdx.y*128, o0 = blockIdx.x*128;
    int tid = threadIdx.x, t_th = tid & 15, co_th = tid >> 4;
    int gbase = o0/2 - 4;

    u64 acc[4][8];
#pragma unroll
    for (int u = 0; u < 4; u++)
#pragma unroll
        for (int j = 0; j < 8; j++) acc[u][j] = 0ULL;

    auto fill = [&](int s, int ci0){
        float* W = Wb + s*WST;
#pragma unroll
        for (int i = tid; i < 4*8*32; i += 256) {
            int q = i & 31, r = i >> 5;
            int ci = r & 7, k = r >> 3;
            cp16z(sptr(W + r*128 + q*4),
                  wt + ((size_t)(k*CIN + ci0+ci))*COUT + co0 + q*4, true);
        }
        float* X = Xb + s*XST;
        for (int i = tid; i < 8*(XPAD/4); i += 256) {
            int ci = i / (XPAD/4), c = i % (XPAD/4);
            int gi = gbase + 4*c;
            bool ok = (gi >= 0) && (gi < Tin);
            const float* src = x + ((size_t)b*CIN + ci0+ci)*Tin + (ok ? gi : 0);
            cp16z(sptr(X + ci*XPAD + 4*c), src, ok);
        }
    };

    fill(0, 0); cpcommit();
#pragma unroll 1
    for (int it = 0; it < NIT; it++) {
        int cur = it & 1;
        if (it+1 < NIT) fill(cur^1, (it+1)*8);
        cpcommit();
        cpwait1();
        __syncthreads();
        const float* W = Wb + cur*WST;
        const float* X = Xb + cur*XST;
#pragma unroll
        for (int ci = 0; ci < 8; ci++) {
            float xr[12];
            const float* xp = X + ci*XPAD + t_th*4;
#pragma unroll
            for (int q = 0; q < 3; q++) {
                float4 v = *reinterpret_cast<const float4*>(xp + 4*q);
                xr[4*q]=v.x; xr[4*q+1]=v.y; xr[4*q+2]=v.z; xr[4*q+3]=v.w;
            }
            u64 xb[6];
#pragma unroll
            for (int u = 0; u < 6; u++) xb[u] = bc2(xr[u+3]);
            u64 wp[4][4];
#pragma unroll
            for (int k = 0; k < 4; k++) {
                const ulonglong2* wq = reinterpret_cast<const ulonglong2*>(W + (k*8+ci)*128 + co_th*8);
                ulonglong2 a = wq[0], bq = wq[1];
                wp[k][0]=a.x; wp[k][1]=a.y; wp[k][2]=bq.x; wp[k][3]=bq.y;
            }
#pragma unroll
            for (int j = 0; j < 8; j++) {
                int ua = ((j+1) >> 1) + 1, ka = (j+1) & 1;
                u64 xa = xb[ua], xv = xb[ua-1];
#pragma unroll
                for (int u = 0; u < 4; u++) {
                    fma2(acc[u][j], wp[ka][u],   xa);
                    fma2(acc[u][j], wp[ka+2][u], xv);
                }
            }
        }
        __syncthreads();
    }

    float bb[8];
    {
        float4 b0 = *reinterpret_cast<const float4*>(&bias[co0+co_th*8]);
        float4 b1 = *reinterpret_cast<const float4*>(&bias[co0+co_th*8+4]);
        bb[0]=b0.x; bb[1]=b0.y; bb[2]=b0.z; bb[3]=b0.w;
        bb[4]=b1.x; bb[5]=b1.y; bb[6]=b1.z; bb[7]=b1.w;
    }
    int tout0 = o0 + t_th*8;
#pragma unroll
    for (int u = 0; u < 4; u++) {
        float ra[8], rb[8];
#pragma unroll
        for (int j = 0; j < 8; j++) {
            float2 f = up2(acc[u][j]);
            ra[j] = fmaxf(f.x + bb[2*u],   0.f);
            rb[j] = fmaxf(f.y + bb[2*u+1], 0.f);
        }
        float* ya = &y[((size_t)b*COUT + co0+co_th*8+2*u)*Tout + tout0];
        float* yb = &y[((size_t)b*COUT + co0+co_th*8+2*u+1)*Tout + tout0];
        *reinterpret_cast<float4*>(ya)   = make_float4(ra[0],ra[1],ra[2],ra[3]);
        *reinterpret_cast<float4*>(ya+4) = make_float4(ra[4],ra[5],ra[6],ra[7]);
        *reinterpret_cast<float4*>(yb)   = make_float4(rb[0],rb[1],rb[2],rb[3]);
        *reinterpret_cast<float4*>(yb+4) = make_float4(rb[4],rb[5],rb[6],rb[7]);
    }
}

// -------- codebook norms --------
__global__ void cbn_k(const float* __restrict__ cb, float* __restrict__ cbn)
{
    int k = blockIdx.x * 2 + (threadIdx.x >> 7);
    int lane = threadIdx.x & 127;
    double a = 0.0;
    for (int d = lane; d < 512; d += 128) {
        float v = cb[(size_t)k*512 + d];
        a += (double)v * (double)v;
    }
    __shared__ double s[256];
    s[threadIdx.x] = a; __syncthreads();
    for (int o = 64; o > 0; o >>= 1) {
        if (lane < o) s[threadIdx.x] += s[threadIdx.x + o];
        __syncthreads();
    }
    if (lane == 0) cbn[k] = (float)s[threadIdx.x];
}

// -------- z row norms --------
__global__ void zn_k(const float* __restrict__ z, float* __restrict__ zn)
{
    int b = blockIdx.x, t = threadIdx.x;
    double a = 0.0;
    for (int d = 0; d < 512; d++) {
        float v = z[((size_t)b*512 + d)*128 + t];
        a += (double)v * (double)v;
    }
    zn[b*128 + t] = (float)a;
}

// -------- VQ score, f32x2 over k-pairs (per-element fp32 chain unchanged) ----
__global__ __launch_bounds__(256)
void vq_score_k(const float* __restrict__ z, const float* __restrict__ cb,
                const float* __restrict__ cbn, const float* __restrict__ zn,
                float* __restrict__ bso, int* __restrict__ bio)
{
    __shared__ float Zs[8][128];
    __shared__ float Cs[8][132];
    __shared__ float RS[128][17];
    __shared__ int   RI[128][17];
    int b = blockIdx.y, kc = blockIdx.x, k0 = kc*128;
    int tid = threadIdx.x, t_th = tid & 15, k_th = tid >> 4;

    u64 accp[8][4];
#pragma unroll
    for (int i = 0; i < 8; i++)
#pragma unroll
        for (int jp = 0; jp < 4; jp++) accp[i][jp] = 0ULL;

    for (int d0 = 0; d0 < 512; d0 += 8) {
        for (int i = tid; i < 1024; i += 256) {
            int t = i & 127, ci = i >> 7;
            Zs[ci][t] = z[((size_t)b*512 + d0+ci)*128 + t];
        }
        for (int i = tid; i < 1024; i += 256) {
            int ci = i & 7, kk = i >> 3;
            Cs[ci][kk] = cb[(size_t)(k0+kk)*512 + d0+ci];
        }
        __syncthreads();
#pragma unroll
        for (int ci = 0; ci < 8; ci++) {
            float zr[8];
            float4 z0 = *reinterpret_cast<const float4*>(&Zs[ci][t_th*8]);
            float4 z1 = *reinterpret_cast<const float4*>(&Zs[ci][t_th*8+4]);
            zr[0]=z0.x; zr[1]=z0.y; zr[2]=z0.z; zr[3]=z0.w;
            zr[4]=z1.x; zr[5]=z1.y; zr[6]=z1.z; zr[7]=z1.w;
            u64 cp[4];
            {
                const ulonglong2* cq = reinterpret_cast<const ulonglong2*>(&Cs[ci][k_th*8]);
                ulonglong2 a = cq[0], bq = cq[1];
                cp[0]=a.x; cp[1]=a.y; cp[2]=bq.x; cp[3]=bq.y;
            }
#pragma unroll
            for (int i = 0; i < 8; i++) {
                u64 zb = bc2(zr[i]);
#pragma unroll
                for (int jp = 0; jp < 4; jp++) fma2(accp[i][jp], cp[jp], zb);
            }
        }
        __syncthreads();
    }

    float znv[8];
#pragma unroll
    for (int i = 0; i < 8; i++) znv[i] = __ldg(&zn[b*128 + t_th*8 + i]);

    float bs[8]; int bi[8];
#pragma unroll
    for (int i = 0; i < 8; i++) { bs[i] = 3.0e38f; bi[i] = 0; }
#pragma unroll
    for (int jp = 0; jp < 4; jp++) {
        int ke = k0 + k_th*8 + 2*jp;
        float cne = __ldg(&cbn[ke]);
        float cno = __ldg(&cbn[ke+1]);
#pragma unroll
        for (int i = 0; i < 8; i++) {
            float2 f = up2(accp[i][jp]);
            float t1 = __fadd_rn(znv[i], cne);
            float s1 = __fsub_rn(t1, __fmul_rn(2.f, f.x));
            if (s1 < bs[i]) { bs[i] = s1; bi[i] = ke; }
            float t2 = __fadd_rn(znv[i], cno);
            float s2 = __fsub_rn(t2, __fmul_rn(2.f, f.y));
            if (s2 < bs[i]) { bs[i] = s2; bi[i] = ke+1; }
        }
    }
#pragma unroll
    for (int i = 0; i < 8; i++) {
        RS[t_th*8+i][k_th] = bs[i];
        RI[t_th*8+i][k_th] = bi[i];
    }
    __syncthreads();
    if (tid < 128) {
        float best = RS[tid][0];
        int bidx = RI[tid][0];
        for (int jj = 1; jj < 16; jj++) {
            float s = RS[tid][jj]; int ii = RI[tid][jj];
            if (s < best || (s == best && ii < bidx)) { best = s; bidx = ii; }
        }
        bso[((size_t)b*4 + kc)*128 + tid] = best;
        bio[((size_t)b*4 + kc)*128 + tid] = bidx;
    }
}

__global__ void vq_combine_k(const float* __restrict__ bso, const int* __restrict__ bio,
                             int* __restrict__ idx, float* __restrict__ outIdx)
{
    int n = blockIdx.x*256 + threadIdx.x;
    if (n >= 64*128) return;
    int b = n >> 7, t = n & 127;
    float best = bso[(size_t)b*4*128 + t];
    int bi = bio[(size_t)b*4*128 + t];
    for (int c = 1; c < 4; c++) {
        float s = bso[((size_t)b*4 + c)*128 + t];
        int ii  = bio[((size_t)b*4 + c)*128 + t];
        if (s < best || (s == best && ii < bi)) { best = s; bi = ii; }
    }
    idx[n] = bi;
    outIdx[n] = (float)bi;
}

__global__ void vq_gather_k(const float* __restrict__ cb, const int* __restrict__ idx,
                            const float* __restrict__ z,
                            float* __restrict__ zq_st, float* __restrict__ zq_raw)
{
    int b = blockIdx.x;
    __shared__ int sidx[128];
    if (threadIdx.x < 128) sidx[threadIdx.x] = idx[b*128 + threadIdx.x];
    __syncthreads();
    int t = threadIdx.x & 127, d0 = threadIdx.x >> 7;
    for (int d = d0; d < 512; d += 2) {
        size_t o = ((size_t)b*512 + d)*128 + t;
        float c  = cb[(size_t)sidx[t]*512 + d];
        float zv = z[o];
        zq_raw[o] = c;
        zq_st[o]  = __fadd_rn(zv, __fsub_rn(c, zv));
    }
}

__global__ void loss_partial_k(const float* __restrict__ z, const float* __restrict__ zq,
                               double* __restrict__ part)
{
    const int N = 64*512*128;
    double a = 0.0;
    for (int i = blockIdx.x*blockDim.x + threadIdx.x; i < N; i += gridDim.x*blockDim.x) {
        float d = __fsub_rn(z[i], zq[i]);
        a += (double)d * (double)d;
    }
    __shared__ double s[256];
    s[threadIdx.x] = a; __syncthreads();
    for (int o = 128; o > 0; o >>= 1) {
        if (threadIdx.x < o) s[threadIdx.x] += s[threadIdx.x+o];
        __syncthreads();
    }
    if (threadIdx.x == 0) part[blockIdx.x] = s[0];
}

__global__ void loss_final_k(const double* __restrict__ part, float* __restrict__ out)
{
    __shared__ double s[256];
    s[threadIdx.x] = part[threadIdx.x]; __syncthreads();
    for (int o = 128; o > 0; o >>= 1) {
        if (threadIdx.x < o) s[threadIdx.x] += s[threadIdx.x+o];
        __syncthreads();
    }
    if (threadIdx.x == 0)
        *out = 0.25f * (float)(s[0] / (double)(64*512*128));
}

extern "C" void kernel_launch(void* const* d_in, const int* in_sizes, int n_in,
                              void* d_out, int out_size)
{
    const float* x    = (const float*)d_in[0];
    const float* ew1  = (const float*)d_in[1];  const float* eb1 = (const float*)d_in[2];
    const float* ew2  = (const float*)d_in[3];  const float* eb2 = (const float*)d_in[4];
    const float* ew3  = (const float*)d_in[5];  const float* eb3 = (const float*)d_in[6];
    const float* ew4  = (const float*)d_in[7];  const float* eb4 = (const float*)d_in[8];
    const float* ew5  = (const float*)d_in[9];  const float* eb5 = (const float*)d_in[10];
    const float* cb   = (const float*)d_in[11];
    const float* dw1  = (const float*)d_in[12]; const float* db1 = (const float*)d_in[13];
    const float* dwt2 = (const float*)d_in[14]; const float* dbt2= (const float*)d_in[15];
    const float* dw3  = (const float*)d_in[16]; const float* db3 = (const float*)d_in[17];
    const float* dwt4 = (const float*)d_in[18]; const float* dbt4= (const float*)d_in[19];
    const float* dw5  = (const float*)d_in[20]; const float* db5 = (const float*)d_in[21];
    float* out = (float*)d_out;

    float *xt, *h1, *h2, *h3, *h4, *z, *zq, *zqr, *g1, *g2, *g3, *g4, *wt, *cbn, *zn, *bs;
    int *bi, *idx; double* part;
    cudaGetSymbolAddress((void**)&xt, g_xt);   cudaGetSymbolAddress((void**)&h1, g_h1);
    cudaGetSymbolAddress((void**)&h2, g_h2);   cudaGetSymbolAddress((void**)&h3, g_h3);
    cudaGetSymbolAddress((void**)&h4, g_h4);   cudaGetSymbolAddress((void**)&z,  g_z);
    cudaGetSymbolAddress((void**)&zq, g_zq);   cudaGetSymbolAddress((void**)&zqr, g_zqr);
    cudaGetSymbolAddress((void**)&g1, g_g1);   cudaGetSymbolAddress((void**)&g2, g_g2);
    cudaGetSymbolAddress((void**)&g3, g_g3);   cudaGetSymbolAddress((void**)&g4, g_g4);
    cudaGetSymbolAddress((void**)&wt, g_wt);
    cudaGetSymbolAddress((void**)&cbn, g_cbn); cudaGetSymbolAddress((void**)&zn, g_zn);
    cudaGetSymbolAddress((void**)&bs, g_bs);   cudaGetSymbolAddress((void**)&bi, g_bi);
    cudaGetSymbolAddress((void**)&idx, g_idx); cudaGetSymbolAddress((void**)&part, g_part);

    const size_t OFF[10] = {0,196608,458752,851968,1900544,2686976,
                            3473408,4521984,4915200,5177344};

    const int SM1 = (2*3*8*128 + 2*8*136)*4;   // 33280
    const int SM2 = (2*4*8*128 + 2*8*264)*4;   // 49664
    const int SMT = (2*4*8*128 + 2*8*72)*4;    // 37376

    cudaFuncSetAttribute(conv1d_k<256,256,3,1,true,false>,  cudaFuncAttributeMaxDynamicSharedMemorySize, SM1);
    cudaFuncSetAttribute(conv1d_k<256,256,4,2,true,false>,  cudaFuncAttributeMaxDynamicSharedMemorySize, SM2);
    cudaFuncSetAttribute(conv1d_k<256,512,3,1,true,false>,  cudaFuncAttributeMaxDynamicSharedMemorySize, SM1);
    cudaFuncSetAttribute(conv1d_k<512,512,4,2,true,false>,  cudaFuncAttributeMaxDynamicSharedMemorySize, SM2);
    cudaFuncSetAttribute(conv1d_k<512,512,3,1,false,false>, cudaFuncAttributeMaxDynamicSharedMemorySize, SM1);
    cudaFuncSetAttribute(conv1d_k<512,512,3,1,true,false>,  cudaFuncAttributeMaxDynamicSharedMemorySize, SM1);
    cudaFuncSetAttribute(conv1d_k<512,256,3,1,true,false>,  cudaFuncAttributeMaxDynamicSharedMemorySize, SM1);
    cudaFuncSetAttribute(conv1d_k<256,256,3,1,false,true>,  cudaFuncAttributeMaxDynamicSharedMemorySize, SM1);
    cudaFuncSetAttribute(convT1d_k<512,512>, cudaFuncAttributeMaxDynamicSharedMemorySize, SMT);
    cudaFuncSetAttribute(convT1d_k<256,256>, cudaFuncAttributeMaxDynamicSharedMemorySize, SMT);

    // weights (one fused transpose) + input transpose
    W10 wargs;
    wargs.p[0]=ew1; wargs.p[1]=ew2; wargs.p[2]=ew3; wargs.p[3]=ew4; wargs.p[4]=ew5;
    wargs.p[5]=dw1; wargs.p[6]=dwt2; wargs.p[7]=dw3; wargs.p[8]=dwt4; wargs.p[9]=dw5;
    wtr_all_k<<<(5373952+255)/256,256>>>(wargs, wt);
    transpose_in_k<<<dim3(16,8,64), dim3(32,8)>>>(x, xt);

    // encoder
    conv1d_k<256,256,3,1,true,false><<<dim3(4,2,64),256,SM1>>>(xt, wt+OFF[0], eb1, h1, 512, 512);
    conv1d_k<256,256,4,2,true,false><<<dim3(2,2,64),256,SM2>>>(h1, wt+OFF[1], eb2, h2, 512, 256);
    conv1d_k<256,512,3,1,true,false><<<dim3(2,4,64),256,SM1>>>(h2, wt+OFF[2], eb3, h3, 256, 256);
    conv1d_k<512,512,4,2,true,false><<<dim3(1,4,64),256,SM2>>>(h3, wt+OFF[3], eb4, h4, 256, 128);
    conv1d_k<512,512,3,1,false,false><<<dim3(1,4,64),256,SM1>>>(h4, wt+OFF[4], eb5, z, 128, 128);
    // VQ
    cbn_k<<<256,256>>>(cb, cbn);
    zn_k<<<64,128>>>(z, zn);
    vq_score_k<<<dim3(4,64),256>>>(z, cb, cbn, zn, bs, bi);
    vq_combine_k<<<32,256>>>(bs, bi, idx, out + 64*512*256);
    vq_gather_k<<<64,256>>>(cb, idx, z, zq, zqr);
    loss_partial_k<<<256,256>>>(z, zqr, part);
    loss_final_k<<<1,256>>>(part, out + 64*512*256 + 64*128);
    // decoder
    conv1d_k<512,512,3,1,true,false><<<dim3(1,4,64),256,SM1>>>(zq, wt+OFF[5], db1, g1, 128, 128);
    convT1d_k<512,512><<<dim3(2,4,64),256,SMT>>>(g1, wt+OFF[6], dbt2, g2, 128, 256);
    conv1d_k<512,256,3,1,true,false><<<dim3(2,2,64),256,SM1>>>(g2, wt+OFF[7], db3, g3, 256, 256);
    convT1d_k<256,256><<<dim3(4,2,64),256,SMT>>>(g3, wt+OFF[8], dbt4, g4, 256, 512);
    conv1d_k<256,256,3,1,false,true><<<dim3(4,2,64),256,SM1>>>(g4, wt+OFF[9], db5, out, 512, 512);
}

// round 11
// speedup vs baseline: 1.1091x; 1.1091x over previous
#include <cuda_runtime.h>
#include <cuda_bf16.h>
typedef unsigned long long u64; typedef unsigned int u32;
__device__ __forceinline__ u64 bc2(float v){ u64 r; asm("mov.b64 %0, {%1,%1};":"=l"(r):"f"(v)); return r; }
__device__ __forceinline__ void fma2(u64& c, u64 a, u64 b){ asm("fma.rn.f32x2 %0, %1, %2, %0;":"+l"(c):"l"(a),"l"(b)); }
__device__ __forceinline__ float2 up2(u64 v){ float lo,hi; asm("mov.b64 {%0,%1}, %2;":"=f"(lo),"=f"(hi):"l"(v)); return make_float2(lo,hi); }
__device__ __forceinline__ u32 sptr(const void* p){ return (u32)__cvta_generic_to_shared(p); }
__device__ __forceinline__ void cp16z(u32 dst, const void* src, bool ok){
    int sz = ok ? 16 : 0;
    asm volatile("cp.async.cg.shared.global [%0], [%1], 16, %2;"::"r"(dst),"l"(src),"r"(sz));
}
__device__ __forceinline__ void cpcommit(){ asm volatile("cp.async.commit_group;"); }
__device__ __forceinline__ void cpwait1(){ asm volatile("cp.async.wait_group 1;"); }

__device__ float g_xt[64*256*512];
__device__ float g_h1[64*256*512];
__device__ float g_h2[64*256*256];
__device__ float g_h3[64*512*256];
__device__ float g_h4[64*512*128];
__device__ float g_z [64*512*128];
__device__ float g_zq[64*512*128];
__device__ float g_zqr[64*512*128];
__device__ float g_g1[64*512*128];
__device__ float g_g2[64*512*256];
__device__ float g_g3[64*256*256];
__device__ float g_g4[64*256*512];
__device__ float g_wt[5373952];
__device__ __nv_bfloat16 g_wbh[1376256];
__device__ __nv_bfloat16 g_wbl[1376256];
__device__ __nv_bfloat16 g_xbh[8388608];
__device__ __nv_bfloat16 g_xbl[8388608];
__device__ float g_cbn[512];
__device__ float g_zn[64*128];
__device__ float g_bs[64*4*128];
__device__ int   g_bi[64*4*128];
__device__ int   g_idx[64*128];
__device__ double g_part[256];

struct W10 { const float* p[10]; };
__global__ void wtr_all_k(W10 a, float* __restrict__ wt)
{
    const int CINL[10]={256,256,256,512,512,512,512,512,256,256};
    const int COUTL[10]={256,256,512,512,512,512,512,256,256,256};
    const int KL[10]={3,4,3,4,3,3,4,3,4,3};
    const int TL[10]={0,0,0,0,0,0,1,0,1,0};
    const int OFF[11]={0,196608,458752,851968,1900544,2686976,3473408,4521984,4915200,5177344,5373952};
    int gi = blockIdx.x*256 + threadIdx.x;
    if (gi >= 5373952) return;
    int l = 0;
#pragma unroll
    for (int q = 1; q < 10; q++) if (gi >= OFF[q]) l = q;
    int i = gi - OFF[l];
    int COUT = COUTL[l], CIN = CINL[l], K = KL[l];
    int co = i % COUT, r = i / COUT, ci = r % CIN, k = r / CIN;
    wt[gi] = TL[l] ? a.p[l][((size_t)ci*COUT+co)*K+k] : a.p[l][((size_t)co*CIN+ci)*K+k];
}

__global__ void wsplit_k(const float* __restrict__ w, __nv_bfloat16* __restrict__ wh,
                         __nv_bfloat16* __restrict__ wl, int CIN, int COUT)
{
    int i = blockIdx.x*256 + threadIdx.x;
    if (i >= COUT*CIN*3) return;
    int ci = i % CIN; int r = i / CIN; int k = r % 3; int co = r / 3;
    float v = w[((size_t)co*CIN + ci)*3 + k];
    __nv_bfloat16 h = __float2bfloat16(v);
    wh[i] = h; wl[i] = __float2bfloat16(v - __bfloat162float(h));
}

__global__ void transpose_in_k(const float* __restrict__ x, float* __restrict__ xt)
{
    __shared__ float tile[32][33];
    int b = blockIdx.z, t0 = blockIdx.x*32, f0 = blockIdx.y*32;
    int tx = threadIdx.x, ty = threadIdx.y;
#pragma unroll
    for (int r = 0; r < 32; r += 8)
        tile[ty+r][tx] = x[((size_t)b*512 + (t0+ty+r))*256 + f0+tx];
    __syncthreads();
#pragma unroll
    for (int r = 0; r < 32; r += 8)
        xt[((size_t)b*256 + (f0+ty+r))*512 + t0+tx] = tile[tx][ty+r];
}

// [B][C][T] fp32 -> [B][T][C] bf16 hi/lo
__global__ void xsplitT_k(const float* __restrict__ x, __nv_bfloat16* __restrict__ xh,
                          __nv_bfloat16* __restrict__ xl, int C, int T)
{
    __shared__ float tile[32][33];
    int b = blockIdx.z, t0 = blockIdx.x*32, c0 = blockIdx.y*32;
    int tx = threadIdx.x, ty = threadIdx.y;
#pragma unroll
    for (int r = 0; r < 32; r += 8)
        tile[ty+r][tx] = x[((size_t)b*C + c0+ty+r)*T + t0+tx];
    __syncthreads();
#pragma unroll
    for (int r = 0; r < 32; r += 8) {
        float v = tile[tx][ty+r];
        __nv_bfloat16 h = __float2bfloat16(v);
        size_t o = ((size_t)b*T + t0+ty+r)*C + c0+tx;
        xh[o] = h; xl[o] = __float2bfloat16(v - __bfloat162float(h));
    }
}

template <int CIN, int COUT, int K, int STRIDE, bool RELU>
__global__ __launch_bounds__(256, 2)
void conv1d_k(const float* __restrict__ x, const float* __restrict__ wt,
              const float* __restrict__ bias, float* __restrict__ y, int Tin, int Tout)
{
    constexpr int XPAD = (STRIDE==1) ? 136 : 264;
    constexpr int NIT = CIN/8, WST = K*8*128, XST = 8*XPAD;
    extern __shared__ float sm[];
    float* Wb = sm; float* Xb = sm + 2*WST;
    int b = blockIdx.z, co0 = blockIdx.y*128, t0 = blockIdx.x*128;
    int tid = threadIdx.x, t_th = tid & 15, co_th = tid >> 4;
    int gbase = t0*STRIDE - 4;
    u64 acc[4][8];
#pragma unroll
    for (int u = 0; u < 4; u++)
#pragma unroll
        for (int j = 0; j < 8; j++) acc[u][j] = 0ULL;
    auto fill = [&](int s, int ci0){
        float* W = Wb + s*WST;
#pragma unroll
        for (int i = tid; i < K*8*32; i += 256) {
            int q = i & 31, r = i >> 5, ci = r & 7, k = r >> 3;
            cp16z(sptr(W + r*128 + q*4), wt + ((size_t)(k*CIN+ci0+ci))*COUT + co0 + q*4, true);
        }
        float* X = Xb + s*XST;
        for (int i = tid; i < 8*(XPAD/4); i += 256) {
            int ci = i/(XPAD/4), c = i%(XPAD/4), gt = gbase + 4*c;
            bool ok = (gt >= 0) && (gt < Tin);
            cp16z(sptr(X + ci*XPAD + 4*c), x + ((size_t)b*CIN+ci0+ci)*Tin + (ok?gt:0), ok);
        }
    };
    fill(0, 0); cpcommit();
#pragma unroll 1
    for (int it = 0; it < NIT; it++) {
        int cur = it & 1;
        if (it+1 < NIT) fill(cur^1, (it+1)*8);
        cpcommit(); cpwait1(); __syncthreads();
        const float* W = Wb + cur*WST; const float* X = Xb + cur*XST;
#pragma unroll
        for (int ci = 0; ci < 8; ci++) {
            constexpr int NXL = (STRIDE==1) ? 4 : 6;
            float xr[NXL*4];
            const float* xp = X + ci*XPAD + t_th*8*STRIDE;
#pragma unroll
            for (int q = 0; q < NXL; q++) {
                float4 v = *reinterpret_cast<const float4*>(xp + 4*q);
                xr[4*q]=v.x; xr[4*q+1]=v.y; xr[4*q+2]=v.z; xr[4*q+3]=v.w;
            }
            u64 wp[K][4];
#pragma unroll
            for (int k = 0; k < K; k++) {
                const ulonglong2* wq = reinterpret_cast<const ulonglong2*>(W + (k*8+ci)*128 + co_th*8);
                ulonglong2 a = wq[0], bq = wq[1];
                wp[k][0]=a.x; wp[k][1]=a.y; wp[k][2]=bq.x; wp[k][3]=bq.y;
            }
            if constexpr (STRIDE==1) {
                u64 x0 = bc2(xr[3]), x1 = bc2(xr[4]);
#pragma unroll
                for (int j = 0; j < 8; j++) {
                    u64 x2 = bc2(xr[j+5]);
#pragma unroll
                    for (int u = 0; u < 4; u++) fma2(acc[u][j], wp[0][u], x0);
#pragma unroll
                    for (int u = 0; u < 4; u++) fma2(acc[u][j], wp[1][u], x1);
#pragma unroll
                    for (int u = 0; u < 4; u++) fma2(acc[u][j], wp[2][u], x2);
                    x0 = x1; x1 = x2;
                }
            } else {
                u64 x0 = bc2(xr[3]), x1 = bc2(xr[4]);
#pragma unroll
                for (int j = 0; j < 8; j++) {
                    u64 x2 = bc2(xr[2*j+5]), x3 = bc2(xr[2*j+6]);
#pragma unroll
                    for (int u = 0; u < 4; u++) fma2(acc[u][j], wp[0][u], x0);
#pragma unroll
                    for (int u = 0; u < 4; u++) fma2(acc[u][j], wp[1][u], x1);
#pragma unroll
                    for (int u = 0; u < 4; u++) fma2(acc[u][j], wp[2][u], x2);
#pragma unroll
                    for (int u = 0; u < 4; u++) fma2(acc[u][j], wp[3][u], x3);
                    x0 = x2; x1 = x3;
                }
            }
        }
        __syncthreads();
    }
    float bb[8];
    {
        float4 b0 = *reinterpret_cast<const float4*>(&bias[co0+co_th*8]);
        float4 b1 = *reinterpret_cast<const float4*>(&bias[co0+co_th*8+4]);
        bb[0]=b0.x; bb[1]=b0.y; bb[2]=b0.z; bb[3]=b0.w;
        bb[4]=b1.x; bb[5]=b1.y; bb[6]=b1.z; bb[7]=b1.w;
    }
    int tout0 = t0 + t_th*8;
#pragma unroll
    for (int u = 0; u < 4; u++) {
        float ra[8], rb[8];
#pragma unroll
        for (int j = 0; j < 8; j++) {
            float2 f = up2(acc[u][j]);
            float va = f.x + bb[2*u], vb = f.y + bb[2*u+1];
            ra[j] = RELU ? fmaxf(va, 0.f) : va;
            rb[j] = RELU ? fmaxf(vb, 0.f) : vb;
        }
        float* ya = &y[((size_t)b*COUT + co0+co_th*8+2*u)*Tout + tout0];
        float* yb = &y[((size_t)b*COUT + co0+co_th*8+2*u+1)*Tout + tout0];
        *reinterpret_cast<float4*>(ya)   = make_float4(ra[0],ra[1],ra[2],ra[3]);
        *reinterpret_cast<float4*>(ya+4) = make_float4(ra[4],ra[5],ra[6],ra[7]);
        *reinterpret_cast<float4*>(yb)   = make_float4(rb[0],rb[1],rb[2],rb[3]);
        *reinterpret_cast<float4*>(yb+4) = make_float4(rb[4],rb[5],rb[6],rb[7]);
    }
}

template <int CIN, int COUT>
__global__ __launch_bounds__(256, 2)
void convT1d_k(const float* __restrict__ x, const float* __restrict__ wt,
               const float* __restrict__ bias, float* __restrict__ y, int Tin, int Tout)
{
    constexpr int XPAD = 72, NIT = CIN/8, WST = 4*8*128, XST = 8*XPAD;
    extern __shared__ float sm[];
    float* Wb = sm; float* Xb = sm + 2*WST;
    int b = blockIdx.z, co0 = blockIdx.y*128, o0 = blockIdx.x*128;
    int tid = threadIdx.x, t_th = tid & 15, co_th = tid >> 4;
    int gbase = o0/2 - 4;
    u64 acc[4][8];
#pragma unroll
    for (int u = 0; u < 4; u++)
#pragma unroll
        for (int j = 0; j < 8; j++) acc[u][j] = 0ULL;
    auto fill = [&](int s, int ci0){
        float* W = Wb + s*WST;
#pragma unroll
        for (int i = tid; i < 4*8*32; i += 256) {
            int q = i & 31, r = i >> 5, ci = r & 7, k = r >> 3;
            cp16z(sptr(W + r*128 + q*4), wt + ((size_t)(k*CIN+ci0+ci))*COUT + co0 + q*4, true);
        }
        float* X = Xb + s*XST;
        for (int i = tid; i < 8*(XPAD/4); i += 256) {
            int ci = i/(XPAD/4), c = i%(XPAD/4), gi = gbase + 4*c;
            bool ok = (gi >= 0) && (gi < Tin);
            cp16z(sptr(X + ci*XPAD + 4*c), x + ((size_t)b*CIN+ci0+ci)*Tin + (ok?gi:0), ok);
        }
    };
    fill(0, 0); cpcommit();
#pragma unroll 1
    for (int it = 0; it < NIT; it++) {
        int cur = it & 1;
        if (it+1 < NIT) fill(cur^1, (it+1)*8);
        cpcommit(); cpwait1(); __syncthreads();
        const float* W = Wb + cur*WST; const float* X = Xb + cur*XST;
#pragma unroll
        for (int ci = 0; ci < 8; ci++) {
            float xr[12];
            const float* xp = X + ci*XPAD + t_th*4;
#pragma unroll
            for (int q = 0; q < 3; q++) {
                float4 v = *reinterpret_cast<const float4*>(xp + 4*q);
                xr[4*q]=v.x; xr[4*q+1]=v.y; xr[4*q+2]=v.z; xr[4*q+3]=v.w;
            }
            u64 xb[6];
#pragma unroll
            for (int u = 0; u < 6; u++) xb[u] = bc2(xr[u+3]);
            u64 wp[4][4];
#pragma unroll
            for (int k = 0; k < 4; k++) {
                const ulonglong2* wq = reinterpret_cast<const ulonglong2*>(W + (k*8+ci)*128 + co_th*8);
                ulonglong2 a = wq[0], bq = wq[1];
                wp[k][0]=a.x; wp[k][1]=a.y; wp[k][2]=bq.x; wp[k][3]=bq.y;
            }
#pragma unroll
            for (int j = 0; j < 8; j++) {
                int ua = ((j+1) >> 1) + 1, ka = (j+1) & 1;
                u64 xa = xb[ua], xv = xb[ua-1];
#pragma unroll
                for (int u = 0; u < 4; u++) {
                    fma2(acc[u][j], wp[ka][u], xa);
                    fma2(acc[u][j], wp[ka+2][u], xv);
                }
            }
        }
        __syncthreads();
    }
    float bb[8];
    {
        float4 b0 = *reinterpret_cast<const float4*>(&bias[co0+co_th*8]);
        float4 b1 = *reinterpret_cast<const float4*>(&bias[co0+co_th*8+4]);
        bb[0]=b0.x; bb[1]=b0.y; bb[2]=b0.z; bb[3]=b0.w;
        bb[4]=b1.x; bb[5]=b1.y; bb[6]=b1.z; bb[7]=b1.w;
    }
    int tout0 = o0 + t_th*8;
#pragma unroll
    for (int u = 0; u < 4; u++) {
        float ra[8], rb[8];
#pragma unroll
        for (int j = 0; j < 8; j++) {
            float2 f = up2(acc[u][j]);
            ra[j] = fmaxf(f.x + bb[2*u], 0.f);
            rb[j] = fmaxf(f.y + bb[2*u+1], 0.f);
        }
        float* ya = &y[((size_t)b*COUT + co0+co_th*8+2*u)*Tout + tout0];
        float* yb = &y[((size_t)b*COUT + co0+co_th*8+2*u+1)*Tout + tout0];
        *reinterpret_cast<float4*>(ya)   = make_float4(ra[0],ra[1],ra[2],ra[3]);
        *reinterpret_cast<float4*>(ya+4) = make_float4(ra[4],ra[5],ra[6],ra[7]);
        *reinterpret_cast<float4*>(yb)   = make_float4(rb[0],rb[1],rb[2],rb[3]);
        *reinterpret_cast<float4*>(yb+4) = make_float4(rb[4],rb[5],rb[6],rb[7]);
    }
}

// HMMA bf16-split conv1d K=3 s=1 p=1 (decoder). x in [B][T][CIN] bf16 h/l.
template <int CIN, int COUT, bool RELU, bool TROUT>
__global__ __launch_bounds__(256, 2)
void convmma_k(const __nv_bfloat16* __restrict__ xh, const __nv_bfloat16* __restrict__ xl,
               const __nv_bfloat16* __restrict__ wh, const __nv_bfloat16* __restrict__ wl,
               const float* __restrict__ bias, float* __restrict__ y, int Tio)
{
    constexpr int NCH = CIN/16;
    constexpr int WB = 36864, XB = 12480;
    extern __shared__ char smm[];
    char* Wb = smm; char* Xb = smm + 2*WB;
    int tid = threadIdx.x, lane = tid & 31, wid = tid >> 5;
    int b = blockIdx.z, co0 = blockIdx.y*128, t0 = blockIdx.x*128;
    int coW = (wid & 3)*32, tW = (wid >> 2)*64;
    float d[2][8][4];
#pragma unroll
    for (int u = 0; u < 2; u++)
#pragma unroll
        for (int v = 0; v < 8; v++)
#pragma unroll
            for (int i = 0; i < 4; i++) d[u][v][i] = 0.f;

    auto fill = [&](int s, int c){
        char* W = Wb + s*WB;
        for (int i = tid; i < 1536; i += 256) {
            int q = i & 1, r = i >> 1, co = r & 127, r2 = r >> 7, k = r2 % 3, w = r2 / 3;
            const __nv_bfloat16* src = (w ? wl : wh) + ((size_t)(co0+co)*3 + k)*CIN + c*16 + q*8;
            cp16z(sptr(W + ((w*3+k)*128 + co)*48 + q*16), src, true);
        }
        char* X = Xb + s*XB;
        for (int i = tid; i < 520; i += 256) {
            int q = i & 1, r = i >> 1, row = r % 130, w = r / 130;
            int gt = t0 - 1 + row;
            bool ok = (gt >= 0) && (gt < Tio);
            const __nv_bfloat16* src = (w ? xl : xh) + ((size_t)b*Tio + (ok?gt:0))*CIN + c*16 + q*8;
            cp16z(sptr(X + w*6240 + row*48 + q*16), src, ok);
        }
    };

    fill(0, 0); cpcommit();
    int r = lane >> 2, cb = (lane & 3)*4;
#pragma unroll 1
    for (int it = 0; it < NCH; it++) {
        int cur = it & 1;
        if (it+1 < NCH) fill(cur^1, it+1);
        cpcommit(); cpwait1(); __syncthreads();
        const char* W = Wb + cur*WB; const char* X = Xb + cur*XB;
#pragma unroll
        for (int p = 0; p < 3; p++) {
            const int wsel = (p == 1), xsel = (p == 2);
#pragma unroll
            for (int k = 0; k < 3; k++) {
                u32 a[2][4];
                const char* aB = W + (wsel*3 + k)*6144 + (coW + r)*48 + cb;
#pragma unroll
                for (int u = 0; u < 2; u++) {
                    const char* p2 = aB + u*16*48;
                    a[u][0] = *(const u32*)p2;        a[u][1] = *(const u32*)(p2 + 8*48);
                    a[u][2] = *(const u32*)(p2 + 16); a[u][3] = *(const u32*)(p2 + 8*48 + 16);
                }
                const char* bB = X + xsel*6240 + (tW + r + k)*48 + cb;
#pragma unroll
                for (int v = 0; v < 8; v++) {
                    u32 b0 = *(const u32*)(bB + v*8*48), b1 = *(const u32*)(bB + v*8*48 + 16);
#pragma unroll
                    for (int u = 0; u < 2; u++)
                        asm volatile("mma.sync.aligned.m16n8k16.row.col.f32.bf16.bf16.f32 "
                            "{%0,%1,%2,%3},{%4,%5,%6,%7},{%8,%9},{%0,%1,%2,%3};"
                            : "+f"(d[u][v][0]), "+f"(d[u][v][1]), "+f"(d[u][v][2]), "+f"(d[u][v][3])
                            : "r"(a[u][0]), "r"(a[u][1]), "r"(a[u][2]), "r"(a[u][3]), "r"(b0), "r"(b1));
                }
            }
        }
        __syncthreads();
    }
    int cp = (lane & 3)*2;
#pragma unroll
    for (int u = 0; u < 2; u++)
#pragma unroll
        for (int v = 0; v < 8; v++) {
            int co = coW + u*16 + r, t = tW + v*8 + cp;
            float b0v = __ldg(&bias[co0+co]), b1v = __ldg(&bias[co0+co+8]);
            float v0 = d[u][v][0] + b0v, v1 = d[u][v][1] + b0v;
            float v2 = d[u][v][2] + b1v, v3 = d[u][v][3] + b1v;
            if (RELU) { v0=fmaxf(v0,0.f); v1=fmaxf(v1,0.f); v2=fmaxf(v2,0.f); v3=fmaxf(v3,0.f); }
            if (!TROUT) {
                *(float2*)&y[((size_t)b*COUT + co0+co)*Tio + t0+t]   = make_float2(v0, v1);
                *(float2*)&y[((size_t)b*COUT + co0+co+8)*Tio + t0+t] = make_float2(v2, v3);
            } else {
                size_t o0 = ((size_t)b*Tio + t0+t)*COUT + co0+co;
                size_t o1 = ((size_t)b*Tio + t0+t+1)*COUT + co0+co;
                y[o0] = v0; y[o1] = v1; y[o0+8] = v2; y[o1+8] = v3;
            }
        }
}

__global__ void cbn_k(const float* __restrict__ cb, float* __restrict__ cbn)
{
    int k = blockIdx.x*2 + (threadIdx.x >> 7), lane = threadIdx.x & 127;
    double a = 0.0;
    for (int d = lane; d < 512; d += 128) { float v = cb[(size_t)k*512+d]; a += (double)v*(double)v; }
    __shared__ double s[256];
    s[threadIdx.x] = a; __syncthreads();
    for (int o = 64; o > 0; o >>= 1) { if (lane < o) s[threadIdx.x] += s[threadIdx.x+o]; __syncthreads(); }
    if (lane == 0) cbn[k] = (float)s[threadIdx.x];
}

__global__ void zn_k(const float* __restrict__ z, float* __restrict__ zn)
{
    int b = blockIdx.x, t = threadIdx.x;
    double a = 0.0;
    for (int d = 0; d < 512; d++) { float v = z[((size_t)b*512+d)*128+t]; a += (double)v*(double)v; }
    zn[b*128+t] = (float)a;
}

__global__ __launch_bounds__(256)
void vq_score_k(const float* __restrict__ z, const float* __restrict__ cb,
                const float* __restrict__ cbn, const float* __restrict__ zn,
                float* __restrict__ bso, int* __restrict__ bio)
{
    __shared__ float Zs[8][128];
    __shared__ float Cs[8][132];
    __shared__ float RS[128][17];
    __shared__ int   RI[128][17];
    int b = blockIdx.y, kc = blockIdx.x, k0 = kc*128;
    int tid = threadIdx.x, t_th = tid & 15, k_th = tid >> 4;
    u64 accp[8][4];
#pragma unroll
    for (int i = 0; i < 8; i++)
#pragma unroll
        for (int jp = 0; jp < 4; jp++) accp[i][jp] = 0ULL;
    for (int d0 = 0; d0 < 512; d0 += 8) {
        for (int i = tid; i < 1024; i += 256) { int t = i & 127, ci = i >> 7; Zs[ci][t] = z[((size_t)b*512+d0+ci)*128+t]; }
        for (int i = tid; i < 1024; i += 256) { int ci = i & 7, kk = i >> 3; Cs[ci][kk] = cb[(size_t)(k0+kk)*512+d0+ci]; }
        __syncthreads();
#pragma unroll
        for (int ci = 0; ci < 8; ci++) {
            float zr[8];
            float4 z0 = *reinterpret_cast<const float4*>(&Zs[ci][t_th*8]);
            float4 z1 = *reinterpret_cast<const float4*>(&Zs[ci][t_th*8+4]);
            zr[0]=z0.x; zr[1]=z0.y; zr[2]=z0.z; zr[3]=z0.w;
            zr[4]=z1.x; zr[5]=z1.y; zr[6]=z1.z; zr[7]=z1.w;
            u64 cp[4];
            const ulonglong2* cq = reinterpret_cast<const ulonglong2*>(&Cs[ci][k_th*8]);
            ulonglong2 a = cq[0], bq = cq[1];
            cp[0]=a.x; cp[1]=a.y; cp[2]=bq.x; cp[3]=bq.y;
#pragma unroll
            for (int i = 0; i < 8; i++) {
                u64 zb = bc2(zr[i]);
#pragma unroll
                for (int jp = 0; jp < 4; jp++) fma2(accp[i][jp], cp[jp], zb);
            }
        }
        __syncthreads();
    }
    float znv[8];
#pragma unroll
    for (int i = 0; i < 8; i++) znv[i] = __ldg(&zn[b*128 + t_th*8 + i]);
    float bs[8]; int bi[8];
#pragma unroll
    for (int i = 0; i < 8; i++) { bs[i] = 3.0e38f; bi[i] = 0; }
#pragma unroll
    for (int jp = 0; jp < 4; jp++) {
        int ke = k0 + k_th*8 + 2*jp;
        float cne = __ldg(&cbn[ke]), cno = __ldg(&cbn[ke+1]);
#pragma unroll
        for (int i = 0; i < 8; i++) {
            float2 f = up2(accp[i][jp]);
            float s1 = __fsub_rn(__fadd_rn(znv[i], cne), __fmul_rn(2.f, f.x));
            if (s1 < bs[i]) { bs[i] = s1; bi[i] = ke; }
            float s2 = __fsub_rn(__fadd_rn(znv[i], cno), __fmul_rn(2.f, f.y));
            if (s2 < bs[i]) { bs[i] = s2; bi[i] = ke+1; }
        }
    }
#pragma unroll
    for (int i = 0; i < 8; i++) { RS[t_th*8+i][k_th] = bs[i]; RI[t_th*8+i][k_th] = bi[i]; }
    __syncthreads();
    if (tid < 128) {
        float best = RS[tid][0]; int bidx = RI[tid][0];
        for (int jj = 1; jj < 16; jj++) {
            float s = RS[tid][jj]; int ii = RI[tid][jj];
            if (s < best || (s == best && ii < bidx)) { best = s; bidx = ii; }
        }
        bso[((size_t)b*4 + kc)*128 + tid] = best;
        bio[((size_t)b*4 + kc)*128 + tid] = bidx;
    }
}

__global__ void vq_combine_k(const float* __restrict__ bso, const int* __restrict__ bio,
                             int* __restrict__ idx, float* __restrict__ outIdx)
{
    int n = blockIdx.x*256 + threadIdx.x;
    if (n >= 64*128) return;
    int b = n >> 7, t = n & 127;
    float best = bso[(size_t)b*4*128 + t];
    int bi = bio[(size_t)b*4*128 + t];
    for (int c = 1; c < 4; c++) {
        float s = bso[((size_t)b*4 + c)*128 + t];
        int ii  = bio[((size_t)b*4 + c)*128 + t];
        if (s < best || (s == best && ii < bi)) { best = s; bi = ii; }
    }
    idx[n] = bi; outIdx[n] = (float)bi;
}

__global__ void vq_gather_k(const float* __restrict__ cb, const int* __restrict__ idx,
                            const float* __restrict__ z,
                            float* __restrict__ zq_st, float* __restrict__ zq_raw)
{
    int b = blockIdx.x;
    __shared__ int sidx[128];
    if (threadIdx.x < 128) sidx[threadIdx.x] = idx[b*128 + threadIdx.x];
    __syncthreads();
    int t = threadIdx.x & 127, d0 = threadIdx.x >> 7;
    for (int d = d0; d < 512; d += 2) {
        size_t o = ((size_t)b*512 + d)*128 + t;
        float c = cb[(size_t)sidx[t]*512 + d], zv = z[o];
        zq_raw[o] = c;
        zq_st[o] = __fadd_rn(zv, __fsub_rn(c, zv));
    }
}

__global__ void loss_partial_k(const float* __restrict__ z, const float* __restrict__ zq,
                               double* __restrict__ part)
{
    const int N = 64*512*128;
    double a = 0.0;
    for (int i = blockIdx.x*blockDim.x + threadIdx.x; i < N; i += gridDim.x*blockDim.x) {
        float d = __fsub_rn(z[i], zq[i]); a += (double)d*(double)d;
    }
    __shared__ double s[256];
    s[threadIdx.x] = a; __syncthreads();
    for (int o = 128; o > 0; o >>= 1) { if (threadIdx.x < o) s[threadIdx.x] += s[threadIdx.x+o]; __syncthreads(); }
    if (threadIdx.x == 0) part[blockIdx.x] = s[0];
}

__global__ void loss_final_k(const double* __restrict__ part, float* __restrict__ out)
{
    __shared__ double s[256];
    s[threadIdx.x] = part[threadIdx.x]; __syncthreads();
    for (int o = 128; o > 0; o >>= 1) { if (threadIdx.x < o) s[threadIdx.x] += s[threadIdx.x+o]; __syncthreads(); }
    if (threadIdx.x == 0) *out = 0.25f * (float)(s[0] / (double)(64*512*128));
}

extern "C" void kernel_launch(void* const* d_in, const int* in_sizes, int n_in,
                              void* d_out, int out_size)
{
    const float* x    = (const float*)d_in[0];
    const float* ew1  = (const float*)d_in[1];  const float* eb1 = (const float*)d_in[2];
    const float* ew2  = (const float*)d_in[3];  const float* eb2 = (const float*)d_in[4];
    const float* ew3  = (const float*)d_in[5];  const float* eb3 = (const float*)d_in[6];
    const float* ew4  = (const float*)d_in[7];  const float* eb4 = (const float*)d_in[8];
    const float* ew5  = (const float*)d_in[9];  const float* eb5 = (const float*)d_in[10];
    const float* cb   = (const float*)d_in[11];
    const float* dw1  = (const float*)d_in[12]; const float* db1 = (const float*)d_in[13];
    const float* dwt2 = (const float*)d_in[14]; const float* dbt2= (const float*)d_in[15];
    const float* dw3  = (const float*)d_in[16]; const float* db3 = (const float*)d_in[17];
    const float* dwt4 = (const float*)d_in[18]; const float* dbt4= (const float*)d_in[19];
    const float* dw5  = (const float*)d_in[20]; const float* db5 = (const float*)d_in[21];
    float* out = (float*)d_out;

    float *xt,*h1,*h2,*h3,*h4,*z,*zq,*zqr,*g1,*g2,*g3,*g4,*wt,*cbn,*zn,*bs;
    __nv_bfloat16 *wbh,*wbl,*xbh,*xbl; int *bi,*idx; double* part;
    cudaGetSymbolAddress((void**)&xt, g_xt);   cudaGetSymbolAddress((void**)&h1, g_h1);
    cudaGetSymbolAddress((void**)&h2, g_h2);   cudaGetSymbolAddress((void**)&h3, g_h3);
    cudaGetSymbolAddress((void**)&h4, g_h4);   cudaGetSymbolAddress((void**)&z,  g_z);
    cudaGetSymbolAddress((void**)&zq, g_zq);   cudaGetSymbolAddress((void**)&zqr, g_zqr);
    cudaGetSymbolAddress((void**)&g1, g_g1);   cudaGetSymbolAddress((void**)&g2, g_g2);
    cudaGetSymbolAddress((void**)&g3, g_g3);   cudaGetSymbolAddress((void**)&g4, g_g4);
    cudaGetSymbolAddress((void**)&wt, g_wt);
    cudaGetSymbolAddress((void**)&wbh, g_wbh); cudaGetSymbolAddress((void**)&wbl, g_wbl);
    cudaGetSymbolAddress((void**)&xbh, g_xbh); cudaGetSymbolAddress((void**)&xbl, g_xbl);
    cudaGetSymbolAddress((void**)&cbn, g_cbn); cudaGetSymbolAddress((void**)&zn, g_zn);
    cudaGetSymbolAddress((void**)&bs, g_bs);   cudaGetSymbolAddress((void**)&bi, g_bi);
    cudaGetSymbolAddress((void**)&idx, g_idx); cudaGetSymbolAddress((void**)&part, g_part);

    const size_t OFF[10] = {0,196608,458752,851968,1900544,2686976,3473408,4521984,4915200,5177344};
    const size_t WB1 = 0, WB3 = 786432, WB5 = 1179648;
    const int SM1 = (2*3*8*128 + 2*8*136)*4;
    const int SM2 = (2*4*8*128 + 2*8*264)*4;
    const int SMT = (2*4*8*128 + 2*8*72)*4;
    const int SMM = 2*(36864 + 12480);   // 98688

    cudaFuncSetAttribute(conv1d_k<256,256,3,1,true>,  cudaFuncAttributeMaxDynamicSharedMemorySize, SM1);
    cudaFuncSetAttribute(conv1d_k<256,256,4,2,true>,  cudaFuncAttributeMaxDynamicSharedMemorySize, SM2);
    cudaFuncSetAttribute(conv1d_k<256,512,3,1,true>,  cudaFuncAttributeMaxDynamicSharedMemorySize, SM1);
    cudaFuncSetAttribute(conv1d_k<512,512,4,2,true>,  cudaFuncAttributeMaxDynamicSharedMemorySize, SM2);
    cudaFuncSetAttribute(conv1d_k<512,512,3,1,false>, cudaFuncAttributeMaxDynamicSharedMemorySize, SM1);
    cudaFuncSetAttribute(convT1d_k<512,512>, cudaFuncAttributeMaxDynamicSharedMemorySize, SMT);
    cudaFuncSetAttribute(convT1d_k<256,256>, cudaFuncAttributeMaxDynamicSharedMemorySize, SMT);
    cudaFuncSetAttribute(convmma_k<512,512,true,false>, cudaFuncAttributeMaxDynamicSharedMemorySize, SMM);
    cudaFuncSetAttribute(convmma_k<512,256,true,false>, cudaFuncAttributeMaxDynamicSharedMemorySize, SMM);
    cudaFuncSetAttribute(convmma_k<256,256,false,true>, cudaFuncAttributeMaxDynamicSharedMemorySize, SMM);

    W10 wargs;
    wargs.p[0]=ew1; wargs.p[1]=ew2; wargs.p[2]=ew3; wargs.p[3]=ew4; wargs.p[4]=ew5;
    wargs.p[5]=dw1; wargs.p[6]=dwt2; wargs.p[7]=dw3; wargs.p[8]=dwt4; wargs.p[9]=dw5;
    wtr_all_k<<<(5373952+255)/256,256>>>(wargs, wt);
    wsplit_k<<<(512*512*3+255)/256,256>>>(dw1, wbh+WB1, wbl+WB1, 512, 512);
    wsplit_k<<<(256*512*3+255)/256,256>>>(dw3, wbh+WB3, wbl+WB3, 512, 256);
    wsplit_k<<<(256*256*3+255)/256,256>>>(dw5, wbh+WB5, wbl+WB5, 256, 256);
    transpose_in_k<<<dim3(16,8,64), dim3(32,8)>>>(x, xt);

    conv1d_k<256,256,3,1,true><<<dim3(4,2,64),256,SM1>>>(xt, wt+OFF[0], eb1, h1, 512, 512);
    conv1d_k<256,256,4,2,true><<<dim3(2,2,64),256,SM2>>>(h1, wt+OFF[1], eb2, h2, 512, 256);
    conv1d_k<256,512,3,1,true><<<dim3(2,4,64),256,SM1>>>(h2, wt+OFF[2], eb3, h3, 256, 256);
    conv1d_k<512,512,4,2,true><<<dim3(1,4,64),256,SM2>>>(h3, wt+OFF[3], eb4, h4, 256, 128);
    conv1d_k<512,512,3,1,false><<<dim3(1,4,64),256,SM1>>>(h4, wt+OFF[4], eb5, z, 128, 128);

    cbn_k<<<256,256>>>(cb, cbn);
    zn_k<<<64,128>>>(z, zn);
    vq_score_k<<<dim3(4,64),256>>>(z, cb, cbn, zn, bs, bi);
    vq_combine_k<<<32,256>>>(bs, bi, idx, out + 64*512*256);
    vq_gather_k<<<64,256>>>(cb, idx, z, zq, zqr);
    loss_partial_k<<<256,256>>>(z, zqr, part);
    loss_final_k<<<1,256>>>(part, out + 64*512*256 + 64*128);

    xsplitT_k<<<dim3(4,16,64), dim3(32,8)>>>(zq, xbh, xbl, 512, 128);
    convmma_k<512,512,true,false><<<dim3(1,4,64),256,SMM>>>(xbh, xbl, wbh+WB1, wbl+WB1, db1, g1, 128);
    convT1d_k<512,512><<<dim3(2,4,64),256,SMT>>>(g1, wt+OFF[6], dbt2, g2, 128, 256);
    xsplitT_k<<<dim3(8,16,64), dim3(32,8)>>>(g2, xbh, xbl, 512, 256);
    convmma_k<512,256,true,false><<<dim3(2,2,64),256,SMM>>>(xbh, xbl, wbh+WB3, wbl+WB3, db3, g3, 256);
    convT1d_k<256,256><<<dim3(4,2,64),256,SMT>>>(g3, wt+OFF[8], dbt4, g4, 256, 512);
    xsplitT_k<<<dim3(16,8,64), dim3(32,8)>>>(g4, xbh, xbl, 256, 512);
    convmma_k<256,256,false,true><<<dim3(4,2,64),256,SMM>>>(xbh, xbl, wbh+WB5, wbl+WB5, db5, out, 512);
}

// round 12
// speedup vs baseline: 1.2199x; 1.0999x over previous
#include <cuda_runtime.h>
#include <cuda_bf16.h>
typedef unsigned long long u64; typedef unsigned int u32;
__device__ __forceinline__ u64 bc2(float v){ u64 r; asm("mov.b64 %0, {%1,%1};":"=l"(r):"f"(v)); return r; }
__device__ __forceinline__ void fma2(u64& c, u64 a, u64 b){ asm("fma.rn.f32x2 %0, %1, %2, %0;":"+l"(c):"l"(a),"l"(b)); }
__device__ __forceinline__ float2 up2(u64 v){ float lo,hi; asm("mov.b64 {%0,%1}, %2;":"=f"(lo),"=f"(hi):"l"(v)); return make_float2(lo,hi); }
__device__ __forceinline__ u32 sptr(const void* p){ return (u32)__cvta_generic_to_shared(p); }
__device__ __forceinline__ void cp16z(u32 dst, const void* src, bool ok){
    int sz = ok ? 16 : 0;
    asm volatile("cp.async.cg.shared.global [%0], [%1], 16, %2;"::"r"(dst),"l"(src),"r"(sz));
}
__device__ __forceinline__ void cpcommit(){ asm volatile("cp.async.commit_group;"); }
__device__ __forceinline__ void cpwait1(){ asm volatile("cp.async.wait_group 1;"); }
#define MMA16816(d0,d1,d2,d3,a0,a1,a2,a3,b0,b1) \
    asm volatile("mma.sync.aligned.m16n8k16.row.col.f32.bf16.bf16.f32 " \
        "{%0,%1,%2,%3},{%4,%5,%6,%7},{%8,%9},{%0,%1,%2,%3};" \
        : "+f"(d0), "+f"(d1), "+f"(d2), "+f"(d3) \
        : "r"(a0), "r"(a1), "r"(a2), "r"(a3), "r"(b0), "r"(b1))

__device__ float g_xt[64*256*512];
__device__ float g_h1[64*256*512];
__device__ float g_h2[64*256*256];
__device__ float g_h3[64*512*256];
__device__ float g_h4[64*512*128];
__device__ float g_z [64*512*128];
__device__ float g_zq[64*512*128];
__device__ float g_zqr[64*512*128];
__device__ float g_g1[64*512*128];
__device__ float g_g2[64*512*256];
__device__ float g_g3[64*256*256];
__device__ float g_g4[64*256*512];
__device__ float g_wt[2686976];
__device__ __nv_bfloat16 g_wbh[2686976];
__device__ __nv_bfloat16 g_wbl[2686976];
__device__ __nv_bfloat16 g_xbh[8388608];
__device__ __nv_bfloat16 g_xbl[8388608];
__device__ float g_cbn[512];
__device__ float g_zn[64*128];
__device__ float g_bs[64*4*128];
__device__ int   g_bi[64*4*128];
__device__ int   g_idx[64*128];
__device__ double g_part[256];

struct W5 { const float* p[5]; };
__global__ void wtr_all_k(W5 a, float* __restrict__ wt)
{
    const int CINL[5]={256,256,256,512,512};
    const int COUTL[5]={256,256,512,512,512};
    const int KL[5]={3,4,3,4,3};
    const int OFF[6]={0,196608,458752,851968,1900544,2686976};
    int gi = blockIdx.x*256 + threadIdx.x;
    if (gi >= 2686976) return;
    int l = 0;
#pragma unroll
    for (int q = 1; q < 5; q++) if (gi >= OFF[q]) l = q;
    int i = gi - OFF[l];
    int COUT = COUTL[l], CIN = CINL[l], K = KL[l];
    int co = i % COUT, r = i / COUT, ci = r % CIN, k = r / CIN;
    wt[gi] = a.p[l][((size_t)co*CIN+ci)*K+k];
}

// conv weights [O][I][3] -> split bf16 [co][k][ci]
__global__ void wsplit_k(const float* __restrict__ w, __nv_bfloat16* __restrict__ wh,
                         __nv_bfloat16* __restrict__ wl, int CIN, int COUT)
{
    int i = blockIdx.x*256 + threadIdx.x;
    if (i >= COUT*CIN*3) return;
    int ci = i % CIN; int r = i / CIN; int k = r % 3; int co = r / 3;
    float v = w[((size_t)co*CIN + ci)*3 + k];
    __nv_bfloat16 h = __float2bfloat16(v);
    wh[i] = h; wl[i] = __float2bfloat16(v - __bfloat162float(h));
}

// convT weights [I][O][4] -> split bf16 [co][k][ci]
__global__ void wsplitT_k(const float* __restrict__ w, __nv_bfloat16* __restrict__ wh,
                          __nv_bfloat16* __restrict__ wl, int CIN, int COUT)
{
    int i = blockIdx.x*256 + threadIdx.x;
    if (i >= COUT*CIN*4) return;
    int ci = i % CIN; int r = i / CIN; int k = r % 4; int co = r / 4;
    float v = w[((size_t)ci*COUT + co)*4 + k];
    __nv_bfloat16 h = __float2bfloat16(v);
    wh[i] = h; wl[i] = __float2bfloat16(v - __bfloat162float(h));
}

__global__ void transpose_in_k(const float* __restrict__ x, float* __restrict__ xt)
{
    __shared__ float tile[32][33];
    int b = blockIdx.z, t0 = blockIdx.x*32, f0 = blockIdx.y*32;
    int tx = threadIdx.x, ty = threadIdx.y;
#pragma unroll
    for (int r = 0; r < 32; r += 8)
        tile[ty+r][tx] = x[((size_t)b*512 + (t0+ty+r))*256 + f0+tx];
    __syncthreads();
#pragma unroll
    for (int r = 0; r < 32; r += 8)
        xt[((size_t)b*256 + (f0+ty+r))*512 + t0+tx] = tile[tx][ty+r];
}

__global__ void xsplitT_k(const float* __restrict__ x, __nv_bfloat16* __restrict__ xh,
                          __nv_bfloat16* __restrict__ xl, int C, int T)
{
    __shared__ float tile[32][33];
    int b = blockIdx.z, t0 = blockIdx.x*32, c0 = blockIdx.y*32;
    int tx = threadIdx.x, ty = threadIdx.y;
#pragma unroll
    for (int r = 0; r < 32; r += 8)
        tile[ty+r][tx] = x[((size_t)b*C + c0+ty+r)*T + t0+tx];
    __syncthreads();
#pragma unroll
    for (int r = 0; r < 32; r += 8) {
        float v = tile[tx][ty+r];
        __nv_bfloat16 h = __float2bfloat16(v);
        size_t o = ((size_t)b*T + t0+ty+r)*C + c0+tx;
        xh[o] = h; xl[o] = __float2bfloat16(v - __bfloat162float(h));
    }
}

template <int CIN, int COUT, int K, int STRIDE, bool RELU>
__global__ __launch_bounds__(256, 2)
void conv1d_k(const float* __restrict__ x, const float* __restrict__ wt,
              const float* __restrict__ bias, float* __restrict__ y, int Tin, int Tout)
{
    constexpr int XPAD = (STRIDE==1) ? 136 : 264;
    constexpr int NIT = CIN/8, WST = K*8*128, XST = 8*XPAD;
    extern __shared__ float sm[];
    float* Wb = sm; float* Xb = sm + 2*WST;
    int b = blockIdx.z, co0 = blockIdx.y*128, t0 = blockIdx.x*128;
    int tid = threadIdx.x, t_th = tid & 15, co_th = tid >> 4;
    int gbase = t0*STRIDE - 4;
    u64 acc[4][8];
#pragma unroll
    for (int u = 0; u < 4; u++)
#pragma unroll
        for (int j = 0; j < 8; j++) acc[u][j] = 0ULL;
    auto fill = [&](int s, int ci0){
        float* W = Wb + s*WST;
#pragma unroll
        for (int i = tid; i < K*8*32; i += 256) {
            int q = i & 31, r = i >> 5, ci = r & 7, k = r >> 3;
            cp16z(sptr(W + r*128 + q*4), wt + ((size_t)(k*CIN+ci0+ci))*COUT + co0 + q*4, true);
        }
        float* X = Xb + s*XST;
        for (int i = tid; i < 8*(XPAD/4); i += 256) {
            int ci = i/(XPAD/4), c = i%(XPAD/4), gt = gbase + 4*c;
            bool ok = (gt >= 0) && (gt < Tin);
            cp16z(sptr(X + ci*XPAD + 4*c), x + ((size_t)b*CIN+ci0+ci)*Tin + (ok?gt:0), ok);
        }
    };
    fill(0, 0); cpcommit();
#pragma unroll 1
    for (int it = 0; it < NIT; it++) {
        int cur = it & 1;
        if (it+1 < NIT) fill(cur^1, (it+1)*8);
        cpcommit(); cpwait1(); __syncthreads();
        const float* W = Wb + cur*WST; const float* X = Xb + cur*XST;
#pragma unroll
        for (int ci = 0; ci < 8; ci++) {
            constexpr int NXL = (STRIDE==1) ? 4 : 6;
            float xr[NXL*4];
            const float* xp = X + ci*XPAD + t_th*8*STRIDE;
#pragma unroll
            for (int q = 0; q < NXL; q++) {
                float4 v = *reinterpret_cast<const float4*>(xp + 4*q);
                xr[4*q]=v.x; xr[4*q+1]=v.y; xr[4*q+2]=v.z; xr[4*q+3]=v.w;
            }
            u64 wp[K][4];
#pragma unroll
            for (int k = 0; k < K; k++) {
                const ulonglong2* wq = reinterpret_cast<const ulonglong2*>(W + (k*8+ci)*128 + co_th*8);
                ulonglong2 a = wq[0], bq = wq[1];
                wp[k][0]=a.x; wp[k][1]=a.y; wp[k][2]=bq.x; wp[k][3]=bq.y;
            }
            if constexpr (STRIDE==1) {
                u64 x0 = bc2(xr[3]), x1 = bc2(xr[4]);
#pragma unroll
                for (int j = 0; j < 8; j++) {
                    u64 x2 = bc2(xr[j+5]);
#pragma unroll
                    for (int u = 0; u < 4; u++) fma2(acc[u][j], wp[0][u], x0);
#pragma unroll
                    for (int u = 0; u < 4; u++) fma2(acc[u][j], wp[1][u], x1);
#pragma unroll
                    for (int u = 0; u < 4; u++) fma2(acc[u][j], wp[2][u], x2);
                    x0 = x1; x1 = x2;
                }
            } else {
                u64 x0 = bc2(xr[3]), x1 = bc2(xr[4]);
#pragma unroll
                for (int j = 0; j < 8; j++) {
                    u64 x2 = bc2(xr[2*j+5]), x3 = bc2(xr[2*j+6]);
#pragma unroll
                    for (int u = 0; u < 4; u++) fma2(acc[u][j], wp[0][u], x0);
#pragma unroll
                    for (int u = 0; u < 4; u++) fma2(acc[u][j], wp[1][u], x1);
#pragma unroll
                    for (int u = 0; u < 4; u++) fma2(acc[u][j], wp[2][u], x2);
#pragma unroll
                    for (int u = 0; u < 4; u++) fma2(acc[u][j], wp[3][u], x3);
                    x0 = x2; x1 = x3;
                }
            }
        }
        __syncthreads();
    }
    float bb[8];
    {
        float4 b0 = *reinterpret_cast<const float4*>(&bias[co0+co_th*8]);
        float4 b1 = *reinterpret_cast<const float4*>(&bias[co0+co_th*8+4]);
        bb[0]=b0.x; bb[1]=b0.y; bb[2]=b0.z; bb[3]=b0.w;
        bb[4]=b1.x; bb[5]=b1.y; bb[6]=b1.z; bb[7]=b1.w;
    }
    int tout0 = t0 + t_th*8;
#pragma unroll
    for (int u = 0; u < 4; u++) {
        float ra[8], rb[8];
#pragma unroll
        for (int j = 0; j < 8; j++) {
            float2 f = up2(acc[u][j]);
            float va = f.x + bb[2*u], vb = f.y + bb[2*u+1];
            ra[j] = RELU ? fmaxf(va, 0.f) : va;
            rb[j] = RELU ? fmaxf(vb, 0.f) : vb;
        }
        float* ya = &y[((size_t)b*COUT + co0+co_th*8+2*u)*Tout + tout0];
        float* yb = &y[((size_t)b*COUT + co0+co_th*8+2*u+1)*Tout + tout0];
        *reinterpret_cast<float4*>(ya)   = make_float4(ra[0],ra[1],ra[2],ra[3]);
        *reinterpret_cast<float4*>(ya+4) = make_float4(ra[4],ra[5],ra[6],ra[7]);
        *reinterpret_cast<float4*>(yb)   = make_float4(rb[0],rb[1],rb[2],rb[3]);
        *reinterpret_cast<float4*>(yb+4) = make_float4(rb[4],rb[5],rb[6],rb[7]);
    }
}

// HMMA bf16-split conv1d K=3 s=1 p=1 (decoder)
template <int CIN, int COUT, bool RELU, bool TROUT>
__global__ __launch_bounds__(256, 2)
void convmma_k(const __nv_bfloat16* __restrict__ xh, const __nv_bfloat16* __restrict__ xl,
               const __nv_bfloat16* __restrict__ wh, const __nv_bfloat16* __restrict__ wl,
               const float* __restrict__ bias, float* __restrict__ y, int Tio)
{
    constexpr int NCH = CIN/16;
    constexpr int WB = 36864, XB = 12480;
    extern __shared__ char smm[];
    char* Wb = smm; char* Xb = smm + 2*WB;
    int tid = threadIdx.x, lane = tid & 31, wid = tid >> 5;
    int b = blockIdx.z, co0 = blockIdx.y*128, t0 = blockIdx.x*128;
    int coW = (wid & 3)*32, tW = (wid >> 2)*64;
    float d[2][8][4];
#pragma unroll
    for (int u = 0; u < 2; u++)
#pragma unroll
        for (int v = 0; v < 8; v++)
#pragma unroll
            for (int i = 0; i < 4; i++) d[u][v][i] = 0.f;
    auto fill = [&](int s, int c){
        char* W = Wb + s*WB;
        for (int i = tid; i < 1536; i += 256) {
            int q = i & 1, r = i >> 1, co = r & 127, r2 = r >> 7, k = r2 % 3, w = r2 / 3;
            const __nv_bfloat16* src = (w ? wl : wh) + ((size_t)(co0+co)*3 + k)*CIN + c*16 + q*8;
            cp16z(sptr(W + ((w*3+k)*128 + co)*48 + q*16), src, true);
        }
        char* X = Xb + s*XB;
        for (int i = tid; i < 520; i += 256) {
            int q = i & 1, r = i >> 1, row = r % 130, w = r / 130;
            int gt = t0 - 1 + row;
            bool ok = (gt >= 0) && (gt < Tio);
            const __nv_bfloat16* src = (w ? xl : xh) + ((size_t)b*Tio + (ok?gt:0))*CIN + c*16 + q*8;
            cp16z(sptr(X + w*6240 + row*48 + q*16), src, ok);
        }
    };
    fill(0, 0); cpcommit();
    int r = lane >> 2, cb = (lane & 3)*4;
#pragma unroll 1
    for (int it = 0; it < NCH; it++) {
        int cur = it & 1;
        if (it+1 < NCH) fill(cur^1, it+1);
        cpcommit(); cpwait1(); __syncthreads();
        const char* W = Wb + cur*WB; const char* X = Xb + cur*XB;
#pragma unroll
        for (int p = 0; p < 3; p++) {
            const int wsel = (p == 1), xsel = (p == 2);
#pragma unroll
            for (int k = 0; k < 3; k++) {
                u32 a[2][4];
                const char* aB = W + (wsel*3 + k)*6144 + (coW + r)*48 + cb;
#pragma unroll
                for (int u = 0; u < 2; u++) {
                    const char* p2 = aB + u*16*48;
                    a[u][0] = *(const u32*)p2;        a[u][1] = *(const u32*)(p2 + 8*48);
                    a[u][2] = *(const u32*)(p2 + 16); a[u][3] = *(const u32*)(p2 + 8*48 + 16);
                }
                const char* bB = X + xsel*6240 + (tW + r + k)*48 + cb;
#pragma unroll
                for (int v = 0; v < 8; v++) {
                    u32 b0 = *(const u32*)(bB + v*8*48), b1 = *(const u32*)(bB + v*8*48 + 16);
#pragma unroll
                    for (int u = 0; u < 2; u++)
                        MMA16816(d[u][v][0], d[u][v][1], d[u][v][2], d[u][v][3],
                                 a[u][0], a[u][1], a[u][2], a[u][3], b0, b1);
                }
            }
        }
        __syncthreads();
    }
    int cp = (lane & 3)*2;
#pragma unroll
    for (int u = 0; u < 2; u++)
#pragma unroll
        for (int v = 0; v < 8; v++) {
            int co = coW + u*16 + r, t = tW + v*8 + cp;
            float b0v = __ldg(&bias[co0+co]), b1v = __ldg(&bias[co0+co+8]);
            float v0 = d[u][v][0] + b0v, v1 = d[u][v][1] + b0v;
            float v2 = d[u][v][2] + b1v, v3 = d[u][v][3] + b1v;
            if (RELU) { v0=fmaxf(v0,0.f); v1=fmaxf(v1,0.f); v2=fmaxf(v2,0.f); v3=fmaxf(v3,0.f); }
            if (!TROUT) {
                *(float2*)&y[((size_t)b*COUT + co0+co)*Tio + t0+t]   = make_float2(v0, v1);
                *(float2*)&y[((size_t)b*COUT + co0+co+8)*Tio + t0+t] = make_float2(v2, v3);
            } else {
                size_t o0 = ((size_t)b*Tio + t0+t)*COUT + co0+co;
                size_t o1 = ((size_t)b*Tio + t0+t+1)*COUT + co0+co;
                y[o0] = v0; y[o1] = v1; y[o0+8] = v2; y[o1+8] = v3;
            }
        }
}

// HMMA bf16-split convT1d K=4 s=2 p=1 (decoder). parity pp: o=2m+pp.
// pp=0: taps (k=1,i=m),(k=3,i=m-1); pp=1: (k=0,i=m+1),(k=2,i=m).
template <int CIN, int COUT>
__global__ __launch_bounds__(256, 1)
void convTmma_k(const __nv_bfloat16* __restrict__ xh, const __nv_bfloat16* __restrict__ xl,
                const __nv_bfloat16* __restrict__ wh, const __nv_bfloat16* __restrict__ wl,
                const float* __restrict__ bias, float* __restrict__ y, int Tout)
{
    const int Tin = Tout >> 1;
    constexpr int NCH = CIN/16;
    constexpr int WB = 49152, XB = 6528;   // W: 2sp*4k*128co*48; X: 2sp*68rows*48
    extern __shared__ char smm[];
    char* Wb = smm; char* Xb = smm + 2*WB;
    int tid = threadIdx.x, lane = tid & 31, wid = tid >> 5;
    int b = blockIdx.z, co0 = blockIdx.y*128, t0 = blockIdx.x*128, m0 = blockIdx.x*64;
    int coW = (wid & 3)*32, mW = (wid >> 2)*32;
    float d[2][2][4][4];
#pragma unroll
    for (int pp = 0; pp < 2; pp++)
#pragma unroll
        for (int u = 0; u < 2; u++)
#pragma unroll
            for (int v = 0; v < 4; v++)
#pragma unroll
                for (int i = 0; i < 4; i++) d[pp][u][v][i] = 0.f;
    auto fill = [&](int s, int c){
        char* W = Wb + s*WB;
        for (int i = tid; i < 2048; i += 256) {
            int q = i & 1, r = i >> 1, co = r & 127, r2 = r >> 7, k = r2 & 3, w = r2 >> 2;
            const __nv_bfloat16* src = (w ? wl : wh) + ((size_t)(co0+co)*4 + k)*CIN + c*16 + q*8;
            cp16z(sptr(W + ((w*4+k)*128 + co)*48 + q*16), src, true);
        }
        char* X = Xb + s*XB;
        for (int i = tid; i < 264; i += 256) {
            int q = i & 1, r = i >> 1, row = r % 66, w = r / 66;
            int gi = m0 - 1 + row;
            bool ok = (gi >= 0) && (gi < Tin);
            const __nv_bfloat16* src = (w ? xl : xh) + ((size_t)b*Tin + (ok?gi:0))*CIN + c*16 + q*8;
            cp16z(sptr(X + w*3264 + row*48 + q*16), src, ok);
        }
    };
    fill(0, 0); cpcommit();
    int r = lane >> 4 ? 0 : 0;  (void)r;
    int rr = lane >> 2, cb = (lane & 3)*4;
    const int KT[2][2] = {{1,3},{0,2}};
    const int IO[2][2] = {{0,-1},{1,0}};
#pragma unroll 1
    for (int it = 0; it < NCH; it++) {
        int cur = it & 1;
        if (it+1 < NCH) fill(cur^1, it+1);
        cpcommit(); cpwait1(); __syncthreads();
        const char* W = Wb + cur*WB; const char* X = Xb + cur*XB;
#pragma unroll
        for (int p = 0; p < 3; p++) {
            const int wsel = (p == 1), xsel = (p == 2);
#pragma unroll
            for (int pp = 0; pp < 2; pp++)
#pragma unroll
                for (int kt = 0; kt < 2; kt++) {
                    int k = KT[pp][kt], io = IO[pp][kt];
                    u32 a[2][4];
                    const char* aB = W + ((wsel*4 + k)*128 + coW + rr)*48 + cb;
#pragma unroll
                    for (int u = 0; u < 2; u++) {
                        const char* p2 = aB + u*16*48;
                        a[u][0] = *(const u32*)p2;        a[u][1] = *(const u32*)(p2 + 8*48);
                        a[u][2] = *(const u32*)(p2 + 16); a[u][3] = *(const u32*)(p2 + 8*48 + 16);
                    }
                    const char* bB = X + xsel*3264 + (mW + rr + io + 1)*48 + cb;
#pragma unroll
                    for (int v = 0; v < 4; v++) {
                        u32 b0 = *(const u32*)(bB + v*8*48), b1 = *(const u32*)(bB + v*8*48 + 16);
#pragma unroll
                        for (int u = 0; u < 2; u++)
                            MMA16816(d[pp][u][v][0], d[pp][u][v][1], d[pp][u][v][2], d[pp][u][v][3],
                                     a[u][0], a[u][1], a[u][2], a[u][3], b0, b1);
                    }
                }
        }
        __syncthreads();
    }
    int cp = (lane & 3)*2;
#pragma unroll
    for (int pp = 0; pp < 2; pp++)
#pragma unroll
        for (int u = 0; u < 2; u++)
#pragma unroll
            for (int v = 0; v < 4; v++) {
                int co = coW + u*16 + rr, m = mW + v*8 + cp;
                float b0v = __ldg(&bias[co0+co]), b1v = __ldg(&bias[co0+co+8]);
                float v0 = fmaxf(d[pp][u][v][0] + b0v, 0.f);
                float v1 = fmaxf(d[pp][u][v][1] + b0v, 0.f);
                float v2 = fmaxf(d[pp][u][v][2] + b1v, 0.f);
                float v3 = fmaxf(d[pp][u][v][3] + b1v, 0.f);
                size_t ya = ((size_t)b*COUT + co0+co)*Tout + t0 + 2*m + pp;
                size_t yb = ((size_t)b*COUT + co0+co+8)*Tout + t0 + 2*m + pp;
                y[ya] = v0; y[ya+2] = v1;
                y[yb] = v2; y[yb+2] = v3;
            }
}

__global__ void cbn_k(const float* __restrict__ cb, float* __restrict__ cbn)
{
    int k = blockIdx.x*2 + (threadIdx.x >> 7), lane = threadIdx.x & 127;
    double a = 0.0;
    for (int d = lane; d < 512; d += 128) { float v = cb[(size_t)k*512+d]; a += (double)v*(double)v; }
    __shared__ double s[256];
    s[threadIdx.x] = a; __syncthreads();
    for (int o = 64; o > 0; o >>= 1) { if (lane < o) s[threadIdx.x] += s[threadIdx.x+o]; __syncthreads(); }
    if (lane == 0) cbn[k] = (float)s[threadIdx.x];
}

__global__ void zn_k(const float* __restrict__ z, float* __restrict__ zn)
{
    int b = blockIdx.x, t = threadIdx.x;
    double a = 0.0;
    for (int d = 0; d < 512; d++) { float v = z[((size_t)b*512+d)*128+t]; a += (double)v*(double)v; }
    zn[b*128+t] = (float)a;
}

__global__ __launch_bounds__(256)
void vq_score_k(const float* __restrict__ z, const float* __restrict__ cb,
                const float* __restrict__ cbn, const float* __restrict__ zn,
                float* __restrict__ bso, int* __restrict__ bio)
{
    __shared__ float Zs[8][128];
    __shared__ float Cs[8][132];
    __shared__ float RS[128][17];
    __shared__ int   RI[128][17];
    int b = blockIdx.y, kc = blockIdx.x, k0 = kc*128;
    int tid = threadIdx.x, t_th = tid & 15, k_th = tid >> 4;
    u64 accp[8][4];
#pragma unroll
    for (int i = 0; i < 8; i++)
#pragma unroll
        for (int jp = 0; jp < 4; jp++) accp[i][jp] = 0ULL;
    for (int d0 = 0; d0 < 512; d0 += 8) {
        for (int i = tid; i < 1024; i += 256) { int t = i & 127, ci = i >> 7; Zs[ci][t] = z[((size_t)b*512+d0+ci)*128+t]; }
        for (int i = tid; i < 1024; i += 256) { int ci = i & 7, kk = i >> 3; Cs[ci][kk] = cb[(size_t)(k0+kk)*512+d0+ci]; }
        __syncthreads();
#pragma unroll
        for (int ci = 0; ci < 8; ci++) {
            float zr[8];
            float4 z0 = *reinterpret_cast<const float4*>(&Zs[ci][t_th*8]);
            float4 z1 = *reinterpret_cast<const float4*>(&Zs[ci][t_th*8+4]);
            zr[0]=z0.x; zr[1]=z0.y; zr[2]=z0.z; zr[3]=z0.w;
            zr[4]=z1.x; zr[5]=z1.y; zr[6]=z1.z; zr[7]=z1.w;
            u64 cp[4];
            const ulonglong2* cq = reinterpret_cast<const ulonglong2*>(&Cs[ci][k_th*8]);
            ulonglong2 a = cq[0], bq = cq[1];
            cp[0]=a.x; cp[1]=a.y; cp[2]=bq.x; cp[3]=bq.y;
#pragma unroll
            for (int i = 0; i < 8; i++) {
                u64 zb = bc2(zr[i]);
#pragma unroll
                for (int jp = 0; jp < 4; jp++) fma2(accp[i][jp], cp[jp], zb);
            }
        }
        __syncthreads();
    }
    float znv[8];
#pragma unroll
    for (int i = 0; i < 8; i++) znv[i] = __ldg(&zn[b*128 + t_th*8 + i]);
    float bs[8]; int bi[8];
#pragma unroll
    for (int i = 0; i < 8; i++) { bs[i] = 3.0e38f; bi[i] = 0; }
#pragma unroll
    for (int jp = 0; jp < 4; jp++) {
        int ke = k0 + k_th*8 + 2*jp;
        float cne = __ldg(&cbn[ke]), cno = __ldg(&cbn[ke+1]);
#pragma unroll
        for (int i = 0; i < 8; i++) {
            float2 f = up2(accp[i][jp]);
            float s1 = __fsub_rn(__fadd_rn(znv[i], cne), __fmul_rn(2.f, f.x));
            if (s1 < bs[i]) { bs[i] = s1; bi[i] = ke; }
            float s2 = __fsub_rn(__fadd_rn(znv[i], cno), __fmul_rn(2.f, f.y));
            if (s2 < bs[i]) { bs[i] = s2; bi[i] = ke+1; }
        }
    }
#pragma unroll
    for (int i = 0; i < 8; i++) { RS[t_th*8+i][k_th] = bs[i]; RI[t_th*8+i][k_th] = bi[i]; }
    __syncthreads();
    if (tid < 128) {
        float best = RS[tid][0]; int bidx = RI[tid][0];
        for (int jj = 1; jj < 16; jj++) {
            float s = RS[tid][jj]; int ii = RI[tid][jj];
            if (s < best || (s == best && ii < bidx)) { best = s; bidx = ii; }
        }
        bso[((size_t)b*4 + kc)*128 + tid] = best;
        bio[((size_t)b*4 + kc)*128 + tid] = bidx;
    }
}

__global__ void vq_combine_k(const float* __restrict__ bso, const int* __restrict__ bio,
                             int* __restrict__ idx, float* __restrict__ outIdx)
{
    int n = blockIdx.x*256 + threadIdx.x;
    if (n >= 64*128) return;
    int b = n >> 7, t = n & 127;
    float best = bso[(size_t)b*4*128 + t];
    int bi = bio[(size_t)b*4*128 + t];
    for (int c = 1; c < 4; c++) {
        float s = bso[((size_t)b*4 + c)*128 + t];
        int ii  = bio[((size_t)b*4 + c)*128 + t];
        if (s < best || (s == best && ii < bi)) { best = s; bi = ii; }
    }
    idx[n] = bi; outIdx[n] = (float)bi;
}

__global__ void vq_gather_k(const float* __restrict__ cb, const int* __restrict__ idx,
                            const float* __restrict__ z,
                            float* __restrict__ zq_st, float* __restrict__ zq_raw)
{
    int b = blockIdx.x;
    __shared__ int sidx[128];
    if (threadIdx.x < 128) sidx[threadIdx.x] = idx[b*128 + threadIdx.x];
    __syncthreads();
    int t = threadIdx.x & 127, d0 = threadIdx.x >> 7;
    for (int d = d0; d < 512; d += 2) {
        size_t o = ((size_t)b*512 + d)*128 + t;
        float c = cb[(size_t)sidx[t]*512 + d], zv = z[o];
        zq_raw[o] = c;
        zq_st[o] = __fadd_rn(zv, __fsub_rn(c, zv));
    }
}

__global__ void loss_partial_k(const float* __restrict__ z, const float* __restrict__ zq,
                               double* __restrict__ part)
{
    const int N = 64*512*128;
    double a = 0.0;
    for (int i = blockIdx.x*blockDim.x + threadIdx.x; i < N; i += gridDim.x*blockDim.x) {
        float d = __fsub_rn(z[i], zq[i]); a += (double)d*(double)d;
    }
    __shared__ double s[256];
    s[threadIdx.x] = a; __syncthreads();
    for (int o = 128; o > 0; o >>= 1) { if (threadIdx.x < o) s[threadIdx.x] += s[threadIdx.x+o]; __syncthreads(); }
    if (threadIdx.x == 0) part[blockIdx.x] = s[0];
}

__global__ void loss_final_k(const double* __restrict__ part, float* __restrict__ out)
{
    __shared__ double s[256];
    s[threadIdx.x] = part[threadIdx.x]; __syncthreads();
    for (int o = 128; o > 0; o >>= 1) { if (threadIdx.x < o) s[threadIdx.x] += s[threadIdx.x+o]; __syncthreads(); }
    if (threadIdx.x == 0) *out = 0.25f * (float)(s[0] / (double)(64*512*128));
}

extern "C" void kernel_launch(void* const* d_in, const int* in_sizes, int n_in,
                              void* d_out, int out_size)
{
    const float* x    = (const float*)d_in[0];
    const float* ew1  = (const float*)d_in[1];  const float* eb1 = (const float*)d_in[2];
    const float* ew2  = (const float*)d_in[3];  const float* eb2 = (const float*)d_in[4];
    const float* ew3  = (const float*)d_in[5];  const float* eb3 = (const float*)d_in[6];
    const float* ew4  = (const float*)d_in[7];  const float* eb4 = (const float*)d_in[8];
    const float* ew5  = (const float*)d_in[9];  const float* eb5 = (const float*)d_in[10];
    const float* cb   = (const float*)d_in[11];
    const float* dw1  = (const float*)d_in[12]; const float* db1 = (const float*)d_in[13];
    const float* dwt2 = (const float*)d_in[14]; const float* dbt2= (const float*)d_in[15];
    const float* dw3  = (const float*)d_in[16]; const float* db3 = (const float*)d_in[17];
    const float* dwt4 = (const float*)d_in[18]; const float* dbt4= (const float*)d_in[19];
    const float* dw5  = (const float*)d_in[20]; const float* db5 = (const float*)d_in[21];
    float* out = (float*)d_out;

    float *xt,*h1,*h2,*h3,*h4,*z,*zq,*zqr,*g1,*g2,*g3,*g4,*wt,*cbn,*zn,*bs;
    __nv_bfloat16 *wbh,*wbl,*xbh,*xbl; int *bi,*idx; double* part;
    cudaGetSymbolAddress((void**)&xt, g_xt);   cudaGetSymbolAddress((void**)&h1, g_h1);
    cudaGetSymbolAddress((void**)&h2, g_h2);   cudaGetSymbolAddress((void**)&h3, g_h3);
    cudaGetSymbolAddress((void**)&h4, g_h4);   cudaGetSymbolAddress((void**)&z,  g_z);
    cudaGetSymbolAddress((void**)&zq, g_zq);   cudaGetSymbolAddress((void**)&zqr, g_zqr);
    cudaGetSymbolAddress((void**)&g1, g_g1);   cudaGetSymbolAddress((void**)&g2, g_g2);
    cudaGetSymbolAddress((void**)&g3, g_g3);   cudaGetSymbolAddress((void**)&g4, g_g4);
    cudaGetSymbolAddress((void**)&wt, g_wt);
    cudaGetSymbolAddress((void**)&wbh, g_wbh); cudaGetSymbolAddress((void**)&wbl, g_wbl);
    cudaGetSymbolAddress((void**)&xbh, g_xbh); cudaGetSymbolAddress((void**)&xbl, g_xbl);
    cudaGetSymbolAddress((void**)&cbn, g_cbn); cudaGetSymbolAddress((void**)&zn, g_zn);
    cudaGetSymbolAddress((void**)&bs, g_bs);   cudaGetSymbolAddress((void**)&bi, g_bi);
    cudaGetSymbolAddress((void**)&idx, g_idx); cudaGetSymbolAddress((void**)&part, g_part);

    const size_t OFF[5] = {0,196608,458752,851968,1900544};
    const size_t WB1 = 0, WB3 = 786432, WB5 = 1179648, WT2 = 1376256, WT4 = 2424832;
    const int SM1 = (2*3*8*128 + 2*8*136)*4;
    const int SM2 = (2*4*8*128 + 2*8*264)*4;
    const int SMM = 2*(36864 + 12480);
    const int SMMT = 2*(49152 + 6528);

    cudaFuncSetAttribute(conv1d_k<256,256,3,1,true>,  cudaFuncAttributeMaxDynamicSharedMemorySize, SM1);
    cudaFuncSetAttribute(conv1d_k<256,256,4,2,true>,  cudaFuncAttributeMaxDynamicSharedMemorySize, SM2);
    cudaFuncSetAttribute(conv1d_k<256,512,3,1,true>,  cudaFuncAttributeMaxDynamicSharedMemorySize, SM1);
    cudaFuncSetAttribute(conv1d_k<512,512,4,2,true>,  cudaFuncAttributeMaxDynamicSharedMemorySize, SM2);
    cudaFuncSetAttribute(conv1d_k<512,512,3,1,false>, cudaFuncAttributeMaxDynamicSharedMemorySize, SM1);
    cudaFuncSetAttribute(convmma_k<512,512,true,false>, cudaFuncAttributeMaxDynamicSharedMemorySize, SMM);
    cudaFuncSetAttribute(convmma_k<512,256,true,false>, cudaFuncAttributeMaxDynamicSharedMemorySize, SMM);
    cudaFuncSetAttribute(convmma_k<256,256,false,true>, cudaFuncAttributeMaxDynamicSharedMemorySize, SMM);
    cudaFuncSetAttribute(convTmma_k<512,512>, cudaFuncAttributeMaxDynamicSharedMemorySize, SMMT);
    cudaFuncSetAttribute(convTmma_k<256,256>, cudaFuncAttributeMaxDynamicSharedMemorySize, SMMT);

    W5 wargs;
    wargs.p[0]=ew1; wargs.p[1]=ew2; wargs.p[2]=ew3; wargs.p[3]=ew4; wargs.p[4]=ew5;
    wtr_all_k<<<(2686976+255)/256,256>>>(wargs, wt);
    wsplit_k<<<(512*512*3+255)/256,256>>>(dw1, wbh+WB1, wbl+WB1, 512, 512);
    wsplit_k<<<(256*512*3+255)/256,256>>>(dw3, wbh+WB3, wbl+WB3, 512, 256);
    wsplit_k<<<(256*256*3+255)/256,256>>>(dw5, wbh+WB5, wbl+WB5, 256, 256);
    wsplitT_k<<<(512*512*4+255)/256,256>>>(dwt2, wbh+WT2, wbl+WT2, 512, 512);
    wsplitT_k<<<(256*256*4+255)/256,256>>>(dwt4, wbh+WT4, wbl+WT4, 256, 256);
    transpose_in_k<<<dim3(16,8,64), dim3(32,8)>>>(x, xt);

    conv1d_k<256,256,3,1,true><<<dim3(4,2,64),256,SM1>>>(xt, wt+OFF[0], eb1, h1, 512, 512);
    conv1d_k<256,256,4,2,true><<<dim3(2,2,64),256,SM2>>>(h1, wt+OFF[1], eb2, h2, 512, 256);
    conv1d_k<256,512,3,1,true><<<dim3(2,4,64),256,SM1>>>(h2, wt+OFF[2], eb3, h3, 256, 256);
    conv1d_k<512,512,4,2,true><<<dim3(1,4,64),256,SM2>>>(h3, wt+OFF[3], eb4, h4, 256, 128);
    conv1d_k<512,512,3,1,false><<<dim3(1,4,64),256,SM1>>>(h4, wt+OFF[4], eb5, z, 128, 128);

    cbn_k<<<256,256>>>(cb, cbn);
    zn_k<<<64,128>>>(z, zn);
    vq_score_k<<<dim3(4,64),256>>>(z, cb, cbn, zn, bs, bi);
    vq_combine_k<<<32,256>>>(bs, bi, idx, out + 64*512*256);
    vq_gather_k<<<64,256>>>(cb, idx, z, zq, zqr);
    loss_partial_k<<<256,256>>>(z, zqr, part);
    loss_final_k<<<1,256>>>(part, out + 64*512*256 + 64*128);

    xsplitT_k<<<dim3(4,16,64), dim3(32,8)>>>(zq, xbh, xbl, 512, 128);
    convmma_k<512,512,true,false><<<dim3(1,4,64),256,SMM>>>(xbh, xbl, wbh+WB1, wbl+WB1, db1, g1, 128);
    xsplitT_k<<<dim3(4,16,64), dim3(32,8)>>>(g1, xbh, xbl, 512, 128);
    convTmma_k<512,512><<<dim3(2,4,64),256,SMMT>>>(xbh, xbl, wbh+WT2, wbl+WT2, dbt2, g2, 256);
    xsplitT_k<<<dim3(8,16,64), dim3(32,8)>>>(g2, xbh, xbl, 512, 256);
    convmma_k<512,256,true,false><<<dim3(2,2,64),256,SMM>>>(xbh, xbl, wbh+WB3, wbl+WB3, db3, g3, 256);
    xsplitT_k<<<dim3(8,8,64), dim3(32,8)>>>(g3, xbh, xbl, 256, 256);
    convTmma_k<256,256><<<dim3(4,2,64),256,SMMT>>>(xbh, xbl, wbh+WT4, wbl+WT4, dbt4, g4, 512);
    xsplitT_k<<<dim3(16,8,64), dim3(32,8)>>>(g4, xbh, xbl, 256, 512);
    convmma_k<256,256,false,true><<<dim3(4,2,64),256,SMM>>>(xbh, xbl, wbh+WB5, wbl+WB5, db5, out, 512);
}